// round 7
// baseline (speedup 1.0000x reference)
#include <cuda_runtime.h>
#include <math.h>

#define BATCH  2
#define CH     512
#define NTOK   4096
#define GROUPS 32
#define CPG    16
#define EPS    1e-6f

#define BK  16
#define QP  520   // quad-layout row pitch (floats): 512 + 8 pad (rotates banks by 8/row)

// ---------------- scratch ----------------
__device__ float g_h [(size_t)BATCH * CH * NTOK];
__device__ float g_q [(size_t)BATCH * CH * NTOK];
__device__ float g_k [(size_t)BATCH * CH * NTOK];
__device__ float g_v [(size_t)BATCH * CH * NTOK];
__device__ float g_ao[(size_t)BATCH * CH * NTOK];
__device__ float g_s [(size_t)BATCH * NTOK * NTOK];
__device__ float g_rsum[(size_t)BATCH * NTOK];

// ---------------- GroupNorm (+ rsum zeroing, fused) ----------------
__global__ void gn_kernel(const float* __restrict__ x,
                          const float* __restrict__ gamma,
                          const float* __restrict__ beta)
{
    // zero rowsum scratch (grid covers it: 64 blocks * 256 = 16384 >= 8192)
    const int gid = blockIdx.x * blockDim.x + threadIdx.x;
    if (gid < BATCH * NTOK) g_rsum[gid] = 0.f;

    const int bg = blockIdx.x;
    const int b = bg / GROUPS, g = bg % GROUPS;
    const size_t base = ((size_t)b * CH + (size_t)g * CPG) * NTOK;
    const float* xp = x + base;
    float* hp = g_h + base;
    const int M = CPG * NTOK;

    float s = 0.f, s2 = 0.f;
    for (int i = threadIdx.x * 4; i < M; i += blockDim.x * 4) {
        float4 v = *(const float4*)&xp[i];
        s  += v.x + v.y + v.z + v.w;
        s2 += v.x*v.x + v.y*v.y + v.z*v.z + v.w*v.w;
    }
    __shared__ float shs[8], shs2[8], shbc[2];
    #pragma unroll
    for (int o = 16; o; o >>= 1) {
        s  += __shfl_xor_sync(0xFFFFFFFFu, s,  o);
        s2 += __shfl_xor_sync(0xFFFFFFFFu, s2, o);
    }
    const int wid = threadIdx.x >> 5, lane = threadIdx.x & 31;
    if (!lane) { shs[wid] = s; shs2[wid] = s2; }
    __syncthreads();
    if (threadIdx.x == 0) {
        float ts = 0.f, ts2 = 0.f;
        #pragma unroll
        for (int i = 0; i < 8; i++) { ts += shs[i]; ts2 += shs2[i]; }
        const float mean = ts / (float)M;
        const float var  = ts2 / (float)M - mean * mean;
        shbc[0] = mean;
        shbc[1] = rsqrtf(var + EPS);
    }
    __syncthreads();
    const float mean = shbc[0], rstd = shbc[1];
    for (int i = threadIdx.x * 4; i < M; i += blockDim.x * 4) {
        const int c = g * CPG + (i >> 12);
        const float ga = gamma[c] * rstd;
        const float be = beta[c] - mean * ga;
        float4 v = *(const float4*)&xp[i];
        float4 o;
        o.x = v.x * ga + be; o.y = v.y * ga + be;
        o.z = v.z * ga + be; o.w = v.w * ga + be;
        *(float4*)&hp[i] = o;
    }
}

// ---------------- quad-layout staging helpers ----------------
// Quad layout: element (k, col), k in [0,16), col in [0,128):
//   smem[(k&3)*QP + col*4 + (k>>2)]
// One LDS.128 at [tig*QP + col*4] yields (k=tig, tig+4, tig+8, tig+12) for `col`.

// ROWMAJOR=true:  element (col,k) at src[col*ld + k]  (k contiguous)
// ROWMAJOR=false: element (k,col) at src[k*ld + col]  (col contiguous)
template<bool ROWMAJOR>
__device__ __forceinline__ void ldchunk(float4& r0, float4& r1,
                                        const float* __restrict__ src, int ld, int tid)
{
    if (ROWMAJOR) {
        const int col = tid >> 2, kq = (tid & 3) << 2;
        r0 = *(const float4*)&src[(size_t)col * ld + kq];
        r1 = *(const float4*)&src[(size_t)(col + 64) * ld + kq];
    } else {
        const int k = tid & 15, c4 = (tid >> 4) << 2;
        r0 = *(const float4*)&src[(size_t)k * ld + c4];
        r1 = *(const float4*)&src[(size_t)k * ld + c4 + 64];
    }
}

template<bool ROWMAJOR>
__device__ __forceinline__ void stchunk(float* __restrict__ dst,
                                        float4 r0, float4 r1, int tid)
{
    if (ROWMAJOR) {
        const int col = tid >> 2, q = tid & 3;
        dst[0 * QP + col * 4 + q] = r0.x;
        dst[1 * QP + col * 4 + q] = r0.y;
        dst[2 * QP + col * 4 + q] = r0.z;
        dst[3 * QP + col * 4 + q] = r0.w;
        const int c1 = col + 64;
        dst[0 * QP + c1 * 4 + q] = r1.x;
        dst[1 * QP + c1 * 4 + q] = r1.y;
        dst[2 * QP + c1 * 4 + q] = r1.z;
        dst[3 * QP + c1 * 4 + q] = r1.w;
    } else {
        const int k = tid & 15, c4 = (tid >> 4) << 2;
        float* row = dst + (k & 3) * QP + (k >> 2);
        row[(c4 + 0) * 4] = r0.x; row[(c4 + 1) * 4] = r0.y;
        row[(c4 + 2) * 4] = r0.z; row[(c4 + 3) * 4] = r0.w;
        row[(c4 + 64) * 4] = r1.x; row[(c4 + 65) * 4] = r1.y;
        row[(c4 + 66) * 4] = r1.z; row[(c4 + 67) * 4] = r1.w;
    }
}

__device__ __forceinline__ unsigned ub(float f) { return __float_as_uint(f); }

// ---------------- tf32 tensor-core GEMM core ----------------
// C[m,n] = scale * sum_k A(m,k)*B(k,n) (+bias[m]) (+resid) [exp + rowsum] [/ colscale[n]]
// A_KC: A row-major (m,k) [k contiguous]; else k-major (k,m).
// B_NC: B k-major (k,n) [n contiguous]; else row-major (n,k).
template<bool A_KC, bool B_NC, bool DO_EXP, bool COLSCALE>
__device__ __forceinline__
void gemm_body(const float* __restrict__ A,
               const float* __restrict__ Bm,
               float* __restrict__ Cm,
               const float* __restrict__ bias,
               const float* __restrict__ resid,
               float* __restrict__ rsum,
               int K, int lda, int ldb, int ldc, float scale,
               int m0, int n0)
{
    // staging convention: ROWMAJOR means "k is the contiguous index"
    constexpr bool AROW = A_KC;      // A row-major (m,k)
    constexpr bool BROW = !B_NC;     // B row-major (n,k)

    __shared__ float SA[2][4 * QP];
    __shared__ float SB[2][4 * QP];

    const int tid = threadIdx.x;
    const int warp = tid >> 5, lane = tid & 31;
    const int wm = (warp >> 2) * 64;
    const int wn = (warp & 3) * 32;
    const int grp = lane >> 2;
    const int tig = lane & 3;

    const float* Ab = A_KC ? (A + (size_t)m0 * lda) : (A + m0);
    const float* Bb = B_NC ? (Bm + n0) : (Bm + (size_t)n0 * ldb);
    const size_t astep = A_KC ? BK : (size_t)BK * lda;
    const size_t bstep = B_NC ? (size_t)BK * ldb : BK;

    const int nslab = K / BK;

    float4 ra0, ra1, rb0, rb1;
    // prologue: slab 0 -> regs -> smem buf0
    ldchunk<AROW>(ra0, ra1, Ab, lda, tid);
    ldchunk<BROW>(rb0, rb1, Bb, ldb, tid);
    stchunk<AROW>(SA[0], ra0, ra1, tid);
    stchunk<BROW>(SB[0], rb0, rb1, tid);
    __syncthreads();

    float acc[4][4][4];
    #pragma unroll
    for (int a = 0; a < 4; a++)
        #pragma unroll
        for (int b = 0; b < 4; b++)
            #pragma unroll
            for (int c = 0; c < 4; c++) acc[a][b][c] = 0.f;

    int buf = 0;
    for (int s = 0; s < nslab; s++) {
        const bool has_next = (s + 1) < nslab;
        if (has_next) {
            ldchunk<AROW>(ra0, ra1, Ab + (size_t)(s + 1) * astep, lda, tid);
            ldchunk<BROW>(rb0, rb1, Bb + (size_t)(s + 1) * bstep, ldb, tid);
        }

        // fragment quads for the whole 16-K slab
        const float* sa = SA[buf] + tig * QP;
        const float* sb = SB[buf] + tig * QP;
        float4 qa0[4], qa1[4], qb[4];
        #pragma unroll
        for (int mi = 0; mi < 4; mi++) {
            const int m = wm + mi * 16 + grp;
            qa0[mi] = *(const float4*)&sa[m * 4];
            qa1[mi] = *(const float4*)&sa[(m + 8) * 4];
        }
        #pragma unroll
        for (int nj = 0; nj < 4; nj++) {
            const int n = wn + nj * 8 + grp;
            qb[nj] = *(const float4*)&sb[n * 4];
        }

        #pragma unroll
        for (int mi = 0; mi < 4; mi++)
            #pragma unroll
            for (int nj = 0; nj < 4; nj++) {
                asm volatile(
                    "mma.sync.aligned.m16n8k8.row.col.f32.tf32.tf32.f32 "
                    "{%0,%1,%2,%3}, {%4,%5,%6,%7}, {%8,%9}, {%0,%1,%2,%3};"
                    : "+f"(acc[mi][nj][0]), "+f"(acc[mi][nj][1]),
                      "+f"(acc[mi][nj][2]), "+f"(acc[mi][nj][3])
                    : "r"(ub(qa0[mi].x)), "r"(ub(qa1[mi].x)),
                      "r"(ub(qa0[mi].y)), "r"(ub(qa1[mi].y)),
                      "r"(ub(qb[nj].x)),  "r"(ub(qb[nj].y)));
            }
        #pragma unroll
        for (int mi = 0; mi < 4; mi++)
            #pragma unroll
            for (int nj = 0; nj < 4; nj++) {
                asm volatile(
                    "mma.sync.aligned.m16n8k8.row.col.f32.tf32.tf32.f32 "
                    "{%0,%1,%2,%3}, {%4,%5,%6,%7}, {%8,%9}, {%0,%1,%2,%3};"
                    : "+f"(acc[mi][nj][0]), "+f"(acc[mi][nj][1]),
                      "+f"(acc[mi][nj][2]), "+f"(acc[mi][nj][3])
                    : "r"(ub(qa0[mi].z)), "r"(ub(qa1[mi].z)),
                      "r"(ub(qa0[mi].w)), "r"(ub(qa1[mi].w)),
                      "r"(ub(qb[nj].z)),  "r"(ub(qb[nj].w)));
            }

        if (has_next) {
            stchunk<AROW>(SA[buf ^ 1], ra0, ra1, tid);
            stchunk<BROW>(SB[buf ^ 1], rb0, rb1, tid);
            __syncthreads();
            buf ^= 1;
        }
    }

    // ---- epilogue
    float inv[4][2];
    if (COLSCALE) {
        #pragma unroll
        for (int nj = 0; nj < 4; nj++) {
            const int n = n0 + wn + nj * 8 + (tig << 1);
            inv[nj][0] = 1.f / rsum[n];
            inv[nj][1] = 1.f / rsum[n + 1];
        }
    }
    float rsA[4], rsB[4];
    #pragma unroll
    for (int mi = 0; mi < 4; mi++) { rsA[mi] = 0.f; rsB[mi] = 0.f; }

    #pragma unroll
    for (int mi = 0; mi < 4; mi++) {
        const int mA = m0 + wm + mi * 16 + grp;
        const int mB = mA + 8;
        const float bvA = bias ? bias[mA] : 0.f;
        const float bvB = bias ? bias[mB] : 0.f;
        #pragma unroll
        for (int nj = 0; nj < 4; nj++) {
            const int n = n0 + wn + nj * 8 + (tig << 1);
            float2 o0, o1;
            o0.x = acc[mi][nj][0] * scale + bvA;
            o0.y = acc[mi][nj][1] * scale + bvA;
            o1.x = acc[mi][nj][2] * scale + bvB;
            o1.y = acc[mi][nj][3] * scale + bvB;
            if (DO_EXP) {
                o0.x = __expf(o0.x); o0.y = __expf(o0.y);
                o1.x = __expf(o1.x); o1.y = __expf(o1.y);
                rsA[mi] += o0.x + o0.y;
                rsB[mi] += o1.x + o1.y;
            }
            if (COLSCALE) {
                o0.x *= inv[nj][0]; o0.y *= inv[nj][1];
                o1.x *= inv[nj][0]; o1.y *= inv[nj][1];
            }
            if (resid) {
                float2 r0 = *(const float2*)&resid[(size_t)mA * ldc + n];
                float2 r1 = *(const float2*)&resid[(size_t)mB * ldc + n];
                o0.x += r0.x; o0.y += r0.y;
                o1.x += r1.x; o1.y += r1.y;
            }
            *(float2*)&Cm[(size_t)mA * ldc + n] = o0;
            *(float2*)&Cm[(size_t)mB * ldc + n] = o1;
        }
    }
    if (DO_EXP) {
        #pragma unroll
        for (int mi = 0; mi < 4; mi++) {
            float a = rsA[mi], b = rsB[mi];
            a += __shfl_xor_sync(0xFFFFFFFFu, a, 1);
            a += __shfl_xor_sync(0xFFFFFFFFu, a, 2);
            b += __shfl_xor_sync(0xFFFFFFFFu, b, 1);
            b += __shfl_xor_sync(0xFFFFFFFFu, b, 2);
            if (tig == 0) {
                const int mA = m0 + wm + mi * 16 + grp;
                atomicAdd(&rsum[mA], a);
                atomicAdd(&rsum[mA + 8], b);
            }
        }
    }
}

template<bool A_KC, bool B_NC, bool DO_EXP, bool COLSCALE>
__global__ __launch_bounds__(256, 2)
void gemm_tc(const float* __restrict__ A,  size_t sAb,
             const float* __restrict__ Bm, size_t sBb,
             float* __restrict__ Cm,       size_t sCb,
             const float* __restrict__ bias,
             const float* __restrict__ resid, size_t sRb,
             float* rsum,
             int K, int lda, int ldb, int ldc, float scale)
{
    const int bz = blockIdx.z;
    gemm_body<A_KC, B_NC, DO_EXP, COLSCALE>(
        A + sAb * bz, Bm + sBb * bz, Cm + sCb * bz,
        bias, resid ? resid + sRb * bz : nullptr,
        rsum ? rsum + (size_t)NTOK * bz : nullptr,
        K, lda, ldb, ldc, scale,
        blockIdx.y * 128, blockIdx.x * 128);
}

struct QKVArgs {
    const float* w[3];
    const float* b[3];
    float*       o[3];
};

__global__ __launch_bounds__(256, 2)
void qkv_tc(QKVArgs args, const float* __restrict__ h)
{
    const int pj = blockIdx.z / BATCH;
    const int bz = blockIdx.z % BATCH;
    const size_t sCN = (size_t)CH * NTOK;
    gemm_body<true, true, false, false>(
        args.w[pj], h + sCN * bz, args.o[pj] + sCN * bz,
        args.b[pj], nullptr, nullptr,
        CH, CH, NTOK, NTOK, 1.f,
        blockIdx.y * 128, blockIdx.x * 128);
}

// ---------------- launcher ----------------
extern "C" void kernel_launch(void* const* d_in, const int* in_sizes, int n_in,
                              void* d_out, int out_size)
{
    const float* x     = (const float*)d_in[0];
    const float* gamma = (const float*)d_in[1];
    const float* beta  = (const float*)d_in[2];
    const float* wq    = (const float*)d_in[3];
    const float* bq    = (const float*)d_in[4];
    const float* wk    = (const float*)d_in[5];
    const float* bk    = (const float*)d_in[6];
    const float* wv    = (const float*)d_in[7];
    const float* bv    = (const float*)d_in[8];
    const float* wo    = (const float*)d_in[9];
    const float* bo    = (const float*)d_in[10];
    float* out = (float*)d_out;

    float *h, *q, *k, *v, *ao, *s, *rsum;
    cudaGetSymbolAddress((void**)&h,    g_h);
    cudaGetSymbolAddress((void**)&q,    g_q);
    cudaGetSymbolAddress((void**)&k,    g_k);
    cudaGetSymbolAddress((void**)&v,    g_v);
    cudaGetSymbolAddress((void**)&ao,   g_ao);
    cudaGetSymbolAddress((void**)&s,    g_s);
    cudaGetSymbolAddress((void**)&rsum, g_rsum);

    const size_t sCN = (size_t)CH * NTOK;
    const size_t sNN = (size_t)NTOK * NTOK;
    const float attn_scale = 0.044194173824159216f;   // 512^-0.5

    // 1) GroupNorm -> g_h  (also zeroes g_rsum)
    gn_kernel<<<BATCH * GROUPS, 256>>>(x, gamma, beta);

    // 2) fused Q/K/V projections
    QKVArgs qa;
    qa.w[0] = wq; qa.w[1] = wk; qa.w[2] = wv;
    qa.b[0] = bq; qa.b[1] = bk; qa.b[2] = bv;
    qa.o[0] = q;  qa.o[1] = k;  qa.o[2] = v;
    dim3 gQKV(NTOK / 128, CH / 128, 3 * BATCH);
    qkv_tc<<<gQKV, 256>>>(qa, h);

    // 3) exp-scores = exp(scale * Q^T K), accumulate rowsums
    dim3 gScore(NTOK / 128, NTOK / 128, BATCH);
    gemm_tc<false, true, true, false><<<gScore, 256>>>(
        q, sCN, k, sCN, s, sNN,
        (const float*)nullptr, (const float*)nullptr, 0, rsum,
        CH, NTOK, NTOK, NTOK, attn_scale);

    // 4) ao = (V * expS^T) / rowsum[n]
    dim3 gAV(NTOK / 128, CH / 128, BATCH);
    gemm_tc<true, false, false, true><<<gAV, 256>>>(
        v, sCN, s, sNN, ao, sCN,
        (const float*)nullptr, (const float*)nullptr, 0, rsum,
        NTOK, NTOK, NTOK, NTOK, 1.f);

    // 5) out = x + Wo * ao + bo
    dim3 gProj(NTOK / 128, CH / 128, BATCH);
    gemm_tc<true, true, false, false><<<gProj, 256>>>(
        wo, 0, ao, sCN, out, sCN, bo,
        x, sCN, (float*)nullptr,
        CH, CH, NTOK, NTOK, 1.f);
}

// round 8
// speedup vs baseline: 1.8588x; 1.8588x over previous
#include <cuda_runtime.h>
#include <math.h>

#define BATCH  2
#define CH     512
#define NTOK   4096
#define GROUPS 32
#define CPG    16
#define EPS    1e-6f

#define BK     16
#define KMP    136    // k-major smem pitch (floats): [k][m], m contiguous
#define MKP    20     // row-major smem pitch: [row][k], k contiguous
#define GT     128    // gemm block threads (4 warps, 2x2 warp grid, 64x64 warp tiles)

// ---------------- scratch ----------------
__device__ float g_h [(size_t)BATCH * CH * NTOK];
__device__ float g_q [(size_t)BATCH * CH * NTOK];
__device__ float g_k [(size_t)BATCH * CH * NTOK];
__device__ float g_v [(size_t)BATCH * CH * NTOK];
__device__ float g_ao[(size_t)BATCH * CH * NTOK];
__device__ float g_s [(size_t)BATCH * NTOK * NTOK];
__device__ float g_rsum[(size_t)BATCH * NTOK];

// ---------------- GroupNorm (+ rsum zeroing) ----------------
__global__ void gn_kernel(const float* __restrict__ x,
                          const float* __restrict__ gamma,
                          const float* __restrict__ beta)
{
    const int gid = blockIdx.x * blockDim.x + threadIdx.x;
    if (gid < BATCH * NTOK) g_rsum[gid] = 0.f;

    const int bg = blockIdx.x;
    const int b = bg / GROUPS, g = bg % GROUPS;
    const size_t base = ((size_t)b * CH + (size_t)g * CPG) * NTOK;
    const float* xp = x + base;
    float* hp = g_h + base;
    const int M = CPG * NTOK;

    float s = 0.f, s2 = 0.f;
    for (int i = threadIdx.x * 4; i < M; i += blockDim.x * 4) {
        float4 v = *(const float4*)&xp[i];
        s  += v.x + v.y + v.z + v.w;
        s2 += v.x*v.x + v.y*v.y + v.z*v.z + v.w*v.w;
    }
    __shared__ float shs[8], shs2[8], shbc[2];
    #pragma unroll
    for (int o = 16; o; o >>= 1) {
        s  += __shfl_xor_sync(0xFFFFFFFFu, s,  o);
        s2 += __shfl_xor_sync(0xFFFFFFFFu, s2, o);
    }
    const int wid = threadIdx.x >> 5, lane = threadIdx.x & 31;
    if (!lane) { shs[wid] = s; shs2[wid] = s2; }
    __syncthreads();
    if (threadIdx.x == 0) {
        float ts = 0.f, ts2 = 0.f;
        #pragma unroll
        for (int i = 0; i < 8; i++) { ts += shs[i]; ts2 += shs2[i]; }
        const float mean = ts / (float)M;
        const float var  = ts2 / (float)M - mean * mean;
        shbc[0] = mean;
        shbc[1] = rsqrtf(var + EPS);
    }
    __syncthreads();
    const float mean = shbc[0], rstd = shbc[1];
    for (int i = threadIdx.x * 4; i < M; i += blockDim.x * 4) {
        const int c = g * CPG + (i >> 12);
        const float ga = gamma[c] * rstd;
        const float be = beta[c] - mean * ga;
        float4 v = *(const float4*)&xp[i];
        float4 o;
        o.x = v.x * ga + be; o.y = v.y * ga + be;
        o.z = v.z * ga + be; o.w = v.w * ga + be;
        *(float4*)&hp[i] = o;
    }
}

// ---------------- cp.async staging ----------------
__device__ __forceinline__ void cpa16(float* dst, const float* src)
{
    unsigned s = (unsigned)__cvta_generic_to_shared(dst);
    asm volatile("cp.async.cg.shared.global [%0], [%1], 16;" :: "r"(s), "l"(src));
}

// KM tile: 16 k-rows x 128 cols -> smem[k*KMP + m]
__device__ __forceinline__ void stage_km(float* dst, const float* src, int ld, int tid)
{
    #pragma unroll
    for (int c = tid; c < 512; c += GT) {
        const int k = c >> 5, m4 = (c & 31) << 2;
        cpa16(dst + k * KMP + m4, src + (size_t)k * ld + m4);
    }
}
// MK tile: 128 rows x 16 k -> smem[row*MKP + k]
__device__ __forceinline__ void stage_mk(float* dst, const float* src, int ld, int tid)
{
    #pragma unroll
    for (int c = tid; c < 512; c += GT) {
        const int row = c >> 2, k4 = (c & 3) << 2;
        cpa16(dst + row * MKP + k4, src + (size_t)row * ld + k4);
    }
}

__device__ __forceinline__ unsigned ubits(float f) { return __float_as_uint(f); }

// ---------------- tf32 tensor-core GEMM core ----------------
// C[m,n] = scale * sum_k A(m,k)*B(k,n) (+bias[m]) (+resid) [exp + rowsum] [/ colscale[n]]
// 2-stage cp.async double buffer; 4 warps, 64x64 warp tiles.
template<bool A_KC, bool B_NC, bool DO_EXP, bool COLSCALE>
__device__ __forceinline__
void gemm_body(const float* __restrict__ A,
               const float* __restrict__ Bm,
               float* __restrict__ Cm,
               const float* __restrict__ bias,
               const float* __restrict__ resid,
               float* __restrict__ rsum,
               int K, int lda, int ldb, int ldc, float scale,
               int m0, int n0)
{
    constexpr int SAF = A_KC ? 128 * MKP : 16 * KMP;
    constexpr int SBF = B_NC ? 16 * KMP : 128 * MKP;
    __shared__ float SA[2][SAF];
    __shared__ float SB[2][SBF];

    const int tid = threadIdx.x;
    const int warp = tid >> 5, lane = tid & 31;
    const int wm = (warp >> 1) * 64;    // 0 or 64
    const int wn = (warp & 1) * 64;     // 0 or 64
    const int grp = lane >> 2;
    const int tig = lane & 3;

    const float* Ab = A_KC ? (A + (size_t)m0 * lda) : (A + m0);
    const float* Bb = B_NC ? (Bm + n0) : (Bm + (size_t)n0 * ldb);

    const int nslab = K / BK;

    // prologue: issue slab 0
    if (A_KC) stage_mk(SA[0], Ab, lda, tid); else stage_km(SA[0], Ab, lda, tid);
    if (B_NC) stage_km(SB[0], Bb, ldb, tid); else stage_mk(SB[0], Bb, ldb, tid);
    asm volatile("cp.async.commit_group;");

    float acc[4][8][4];
    #pragma unroll
    for (int a = 0; a < 4; a++)
        #pragma unroll
        for (int b = 0; b < 8; b++)
            #pragma unroll
            for (int c = 0; c < 4; c++) acc[a][b][c] = 0.f;

    int buf = 0;
    for (int s = 0; s < nslab; s++) {
        asm volatile("cp.async.wait_group 0;");
        __syncthreads();

        if (s + 1 < nslab) {
            const size_t ko = (size_t)(s + 1) * BK;
            const float* As = A_KC ? (Ab + ko) : (Ab + ko * lda);
            const float* Bs = B_NC ? (Bb + ko * ldb) : (Bb + ko);
            const int nb = buf ^ 1;
            if (A_KC) stage_mk(SA[nb], As, lda, tid); else stage_km(SA[nb], As, lda, tid);
            if (B_NC) stage_km(SB[nb], Bs, ldb, tid); else stage_mk(SB[nb], Bs, ldb, tid);
            asm volatile("cp.async.commit_group;");
        }

        const float* sa = SA[buf];
        const float* sb = SB[buf];
        #pragma unroll
        for (int kc = 0; kc < BK; kc += 8) {
            const int ka = kc + tig, kb = kc + tig + 4;
            unsigned af[4][4], bf[8][2];
            #pragma unroll
            for (int mi = 0; mi < 4; mi++) {
                const int m = wm + mi * 16 + grp;
                if (A_KC) {
                    af[mi][0] = ubits(sa[m * MKP + ka]);
                    af[mi][1] = ubits(sa[(m + 8) * MKP + ka]);
                    af[mi][2] = ubits(sa[m * MKP + kb]);
                    af[mi][3] = ubits(sa[(m + 8) * MKP + kb]);
                } else {
                    af[mi][0] = ubits(sa[ka * KMP + m]);
                    af[mi][1] = ubits(sa[ka * KMP + m + 8]);
                    af[mi][2] = ubits(sa[kb * KMP + m]);
                    af[mi][3] = ubits(sa[kb * KMP + m + 8]);
                }
            }
            #pragma unroll
            for (int nj = 0; nj < 8; nj++) {
                const int n = wn + nj * 8 + grp;
                if (B_NC) {
                    bf[nj][0] = ubits(sb[ka * KMP + n]);
                    bf[nj][1] = ubits(sb[kb * KMP + n]);
                } else {
                    bf[nj][0] = ubits(sb[n * MKP + ka]);
                    bf[nj][1] = ubits(sb[n * MKP + kb]);
                }
            }
            #pragma unroll
            for (int mi = 0; mi < 4; mi++)
                #pragma unroll
                for (int nj = 0; nj < 8; nj++) {
                    asm volatile(
                        "mma.sync.aligned.m16n8k8.row.col.f32.tf32.tf32.f32 "
                        "{%0,%1,%2,%3}, {%4,%5,%6,%7}, {%8,%9}, {%0,%1,%2,%3};"
                        : "+f"(acc[mi][nj][0]), "+f"(acc[mi][nj][1]),
                          "+f"(acc[mi][nj][2]), "+f"(acc[mi][nj][3])
                        : "r"(af[mi][0]), "r"(af[mi][1]),
                          "r"(af[mi][2]), "r"(af[mi][3]),
                          "r"(bf[nj][0]), "r"(bf[nj][1]));
                }
        }
        buf ^= 1;
    }

    // ---- epilogue
    float inv[8][2];
    if (COLSCALE) {
        #pragma unroll
        for (int nj = 0; nj < 8; nj++) {
            const int n = n0 + wn + nj * 8 + (tig << 1);
            inv[nj][0] = 1.f / rsum[n];
            inv[nj][1] = 1.f / rsum[n + 1];
        }
    }
    float rsA[4], rsB[4];
    #pragma unroll
    for (int mi = 0; mi < 4; mi++) { rsA[mi] = 0.f; rsB[mi] = 0.f; }

    #pragma unroll
    for (int mi = 0; mi < 4; mi++) {
        const int mA = m0 + wm + mi * 16 + grp;
        const int mB = mA + 8;
        const float bvA = bias ? bias[mA] : 0.f;
        const float bvB = bias ? bias[mB] : 0.f;
        #pragma unroll
        for (int nj = 0; nj < 8; nj++) {
            const int n = n0 + wn + nj * 8 + (tig << 1);
            float2 o0, o1;
            o0.x = acc[mi][nj][0] * scale + bvA;
            o0.y = acc[mi][nj][1] * scale + bvA;
            o1.x = acc[mi][nj][2] * scale + bvB;
            o1.y = acc[mi][nj][3] * scale + bvB;
            if (DO_EXP) {
                o0.x = __expf(o0.x); o0.y = __expf(o0.y);
                o1.x = __expf(o1.x); o1.y = __expf(o1.y);
                rsA[mi] += o0.x + o0.y;
                rsB[mi] += o1.x + o1.y;
            }
            if (COLSCALE) {
                o0.x *= inv[nj][0]; o0.y *= inv[nj][1];
                o1.x *= inv[nj][0]; o1.y *= inv[nj][1];
            }
            if (resid) {
                float2 r0 = *(const float2*)&resid[(size_t)mA * ldc + n];
                float2 r1 = *(const float2*)&resid[(size_t)mB * ldc + n];
                o0.x += r0.x; o0.y += r0.y;
                o1.x += r1.x; o1.y += r1.y;
            }
            *(float2*)&Cm[(size_t)mA * ldc + n] = o0;
            *(float2*)&Cm[(size_t)mB * ldc + n] = o1;
        }
    }
    if (DO_EXP) {
        #pragma unroll
        for (int mi = 0; mi < 4; mi++) {
            float a = rsA[mi], b = rsB[mi];
            a += __shfl_xor_sync(0xFFFFFFFFu, a, 1);
            a += __shfl_xor_sync(0xFFFFFFFFu, a, 2);
            b += __shfl_xor_sync(0xFFFFFFFFu, b, 1);
            b += __shfl_xor_sync(0xFFFFFFFFu, b, 2);
            if (tig == 0) {
                const int mA = m0 + wm + mi * 16 + grp;
                atomicAdd(&rsum[mA], a);
                atomicAdd(&rsum[mA + 8], b);
            }
        }
    }
}

template<bool A_KC, bool B_NC, bool DO_EXP, bool COLSCALE>
__global__ __launch_bounds__(GT, 2)
void gemm_tc(const float* __restrict__ A,  size_t sAb,
             const float* __restrict__ Bm, size_t sBb,
             float* __restrict__ Cm,       size_t sCb,
             const float* __restrict__ bias,
             const float* __restrict__ resid, size_t sRb,
             float* rsum,
             int K, int lda, int ldb, int ldc, float scale)
{
    const int bz = blockIdx.z;
    gemm_body<A_KC, B_NC, DO_EXP, COLSCALE>(
        A + sAb * bz, Bm + sBb * bz, Cm + sCb * bz,
        bias, resid ? resid + sRb * bz : nullptr,
        rsum ? rsum + (size_t)NTOK * bz : nullptr,
        K, lda, ldb, ldc, scale,
        blockIdx.y * 128, blockIdx.x * 128);
}

struct QKVArgs {
    const float* w[3];
    const float* b[3];
    float*       o[3];
};

__global__ __launch_bounds__(GT, 2)
void qkv_tc(QKVArgs args, const float* __restrict__ h)
{
    const int pj = blockIdx.z / BATCH;
    const int bz = blockIdx.z % BATCH;
    const size_t sCN = (size_t)CH * NTOK;
    gemm_body<true, true, false, false>(
        args.w[pj], h + sCN * bz, args.o[pj] + sCN * bz,
        args.b[pj], nullptr, nullptr,
        CH, CH, NTOK, NTOK, 1.f,
        blockIdx.y * 128, blockIdx.x * 128);
}

// ---------------- launcher ----------------
extern "C" void kernel_launch(void* const* d_in, const int* in_sizes, int n_in,
                              void* d_out, int out_size)
{
    const float* x     = (const float*)d_in[0];
    const float* gamma = (const float*)d_in[1];
    const float* beta  = (const float*)d_in[2];
    const float* wq    = (const float*)d_in[3];
    const float* bq    = (const float*)d_in[4];
    const float* wk    = (const float*)d_in[5];
    const float* bk    = (const float*)d_in[6];
    const float* wv    = (const float*)d_in[7];
    const float* bv    = (const float*)d_in[8];
    const float* wo    = (const float*)d_in[9];
    const float* bo    = (const float*)d_in[10];
    float* out = (float*)d_out;

    float *h, *q, *k, *v, *ao, *s, *rsum;
    cudaGetSymbolAddress((void**)&h,    g_h);
    cudaGetSymbolAddress((void**)&q,    g_q);
    cudaGetSymbolAddress((void**)&k,    g_k);
    cudaGetSymbolAddress((void**)&v,    g_v);
    cudaGetSymbolAddress((void**)&ao,   g_ao);
    cudaGetSymbolAddress((void**)&s,    g_s);
    cudaGetSymbolAddress((void**)&rsum, g_rsum);

    const size_t sCN = (size_t)CH * NTOK;
    const size_t sNN = (size_t)NTOK * NTOK;
    const float attn_scale = 0.044194173824159216f;   // 512^-0.5

    // 1) GroupNorm -> g_h  (also zeroes g_rsum)
    gn_kernel<<<BATCH * GROUPS, 256>>>(x, gamma, beta);

    // 2) fused Q/K/V projections
    QKVArgs qa;
    qa.w[0] = wq; qa.w[1] = wk; qa.w[2] = wv;
    qa.b[0] = bq; qa.b[1] = bk; qa.b[2] = bv;
    qa.o[0] = q;  qa.o[1] = k;  qa.o[2] = v;
    dim3 gQKV(NTOK / 128, CH / 128, 3 * BATCH);
    qkv_tc<<<gQKV, GT>>>(qa, h);

    // 3) exp-scores = exp(scale * Q^T K), accumulate rowsums
    dim3 gScore(NTOK / 128, NTOK / 128, BATCH);
    gemm_tc<false, true, true, false><<<gScore, GT>>>(
        q, sCN, k, sCN, s, sNN,
        (const float*)nullptr, (const float*)nullptr, 0, rsum,
        CH, NTOK, NTOK, NTOK, attn_scale);

    // 4) ao = (V * expS^T) / rowsum[n]
    dim3 gAV(NTOK / 128, CH / 128, BATCH);
    gemm_tc<true, false, false, true><<<gAV, GT>>>(
        v, sCN, s, sNN, ao, sCN,
        (const float*)nullptr, (const float*)nullptr, 0, rsum,
        NTOK, NTOK, NTOK, NTOK, 1.f);

    // 5) out = x + Wo * ao + bo
    dim3 gProj(NTOK / 128, CH / 128, BATCH);
    gemm_tc<true, true, false, false><<<gProj, GT>>>(
        wo, 0, ao, sCN, out, sCN, bo,
        x, sCN, (float*)nullptr,
        CH, CH, NTOK, NTOK, 1.f);
}

// round 9
// speedup vs baseline: 1.8778x; 1.0102x over previous
#include <cuda_runtime.h>
#include <math.h>

#define BATCH  2
#define CH     512
#define NTOK   4096
#define GROUPS 32
#define CPG    16
#define EPS    1e-6f

#define BK     16
#define KMP    136    // k-major smem pitch (floats): [k][m], m contiguous
#define MKP    20     // row-major smem pitch: [row][k], k contiguous
#define GT     128    // gemm block threads (4 warps, 2x2 warp grid, 64x64 warp tiles)
#define NSTG   3      // pipeline stages

// ---------------- scratch ----------------
__device__ float g_h [(size_t)BATCH * CH * NTOK];
__device__ float g_q [(size_t)BATCH * CH * NTOK];
__device__ float g_k [(size_t)BATCH * CH * NTOK];
__device__ float g_v [(size_t)BATCH * CH * NTOK];
__device__ float g_ao[(size_t)BATCH * CH * NTOK];
__device__ float g_s [(size_t)BATCH * NTOK * NTOK];
__device__ float g_rsum[(size_t)BATCH * NTOK];

// ---------------- GroupNorm (+ rsum zeroing) ----------------
__global__ void gn_kernel(const float* __restrict__ x,
                          const float* __restrict__ gamma,
                          const float* __restrict__ beta)
{
    const int gid = blockIdx.x * blockDim.x + threadIdx.x;
    if (gid < BATCH * NTOK) g_rsum[gid] = 0.f;

    const int bg = blockIdx.x;
    const int b = bg / GROUPS, g = bg % GROUPS;
    const size_t base = ((size_t)b * CH + (size_t)g * CPG) * NTOK;
    const float* xp = x + base;
    float* hp = g_h + base;
    const int M = CPG * NTOK;

    float s = 0.f, s2 = 0.f;
    for (int i = threadIdx.x * 4; i < M; i += blockDim.x * 4) {
        float4 v = *(const float4*)&xp[i];
        s  += v.x + v.y + v.z + v.w;
        s2 += v.x*v.x + v.y*v.y + v.z*v.z + v.w*v.w;
    }
    __shared__ float shs[8], shs2[8], shbc[2];
    #pragma unroll
    for (int o = 16; o; o >>= 1) {
        s  += __shfl_xor_sync(0xFFFFFFFFu, s,  o);
        s2 += __shfl_xor_sync(0xFFFFFFFFu, s2, o);
    }
    const int wid = threadIdx.x >> 5, lane = threadIdx.x & 31;
    if (!lane) { shs[wid] = s; shs2[wid] = s2; }
    __syncthreads();
    if (threadIdx.x == 0) {
        float ts = 0.f, ts2 = 0.f;
        #pragma unroll
        for (int i = 0; i < 8; i++) { ts += shs[i]; ts2 += shs2[i]; }
        const float mean = ts / (float)M;
        const float var  = ts2 / (float)M - mean * mean;
        shbc[0] = mean;
        shbc[1] = rsqrtf(var + EPS);
    }
    __syncthreads();
    const float mean = shbc[0], rstd = shbc[1];
    for (int i = threadIdx.x * 4; i < M; i += blockDim.x * 4) {
        const int c = g * CPG + (i >> 12);
        const float ga = gamma[c] * rstd;
        const float be = beta[c] - mean * ga;
        float4 v = *(const float4*)&xp[i];
        float4 o;
        o.x = v.x * ga + be; o.y = v.y * ga + be;
        o.z = v.z * ga + be; o.w = v.w * ga + be;
        *(float4*)&hp[i] = o;
    }
}

// ---------------- cp.async staging ----------------
__device__ __forceinline__ void cpa16(float* dst, const float* src)
{
    unsigned s = (unsigned)__cvta_generic_to_shared(dst);
    asm volatile("cp.async.cg.shared.global [%0], [%1], 16;" :: "r"(s), "l"(src));
}

// KM tile: 16 k-rows x 128 cols -> smem[k*KMP + m]
__device__ __forceinline__ void stage_km(float* dst, const float* src, int ld, int tid)
{
    #pragma unroll
    for (int c = tid; c < 512; c += GT) {
        const int k = c >> 5, m4 = (c & 31) << 2;
        cpa16(dst + k * KMP + m4, src + (size_t)k * ld + m4);
    }
}
// MK tile: 128 rows x 16 k -> smem[row*MKP + k]
__device__ __forceinline__ void stage_mk(float* dst, const float* src, int ld, int tid)
{
    #pragma unroll
    for (int c = tid; c < 512; c += GT) {
        const int row = c >> 2, k4 = (c & 3) << 2;
        cpa16(dst + row * MKP + k4, src + (size_t)row * ld + k4);
    }
}

__device__ __forceinline__ unsigned ubits(float f) { return __float_as_uint(f); }

// ---------------- tf32 tensor-core GEMM core ----------------
// C[m,n] = scale * sum_k A(m,k)*B(k,n) (+bias[m]) (+resid) [exp + rowsum] [/ colscale[n]]
// 3-stage cp.async ring in dynamic smem; 4 warps, 64x64 warp tiles.
template<bool A_KC, bool B_NC, bool DO_EXP, bool COLSCALE>
__device__ __forceinline__
void gemm_body(float* __restrict__ dyn,
               const float* __restrict__ A,
               const float* __restrict__ Bm,
               float* __restrict__ Cm,
               const float* __restrict__ bias,
               const float* __restrict__ resid,
               float* __restrict__ rsum,
               int K, int lda, int ldb, int ldc, float scale,
               int m0, int n0)
{
    constexpr int SAF = A_KC ? 128 * MKP : 16 * KMP;
    constexpr int SBF = B_NC ? 16 * KMP : 128 * MKP;
    float* SA = dyn;                  // [NSTG][SAF]
    float* SB = dyn + NSTG * SAF;     // [NSTG][SBF]

    const int tid = threadIdx.x;
    const int warp = tid >> 5, lane = tid & 31;
    const int wm = (warp >> 1) * 64;    // 0 or 64
    const int wn = (warp & 1) * 64;     // 0 or 64
    const int grp = lane >> 2;
    const int tig = lane & 3;

    const float* Ab = A_KC ? (A + (size_t)m0 * lda) : (A + m0);
    const float* Bb = B_NC ? (Bm + n0) : (Bm + (size_t)n0 * ldb);
    const size_t astep = A_KC ? BK : (size_t)BK * lda;
    const size_t bstep = B_NC ? (size_t)BK * ldb : BK;

    const int nslab = K / BK;

    // prologue: issue slabs 0 and 1
    if (A_KC) stage_mk(SA, Ab, lda, tid); else stage_km(SA, Ab, lda, tid);
    if (B_NC) stage_km(SB, Bb, ldb, tid); else stage_mk(SB, Bb, ldb, tid);
    asm volatile("cp.async.commit_group;");
    if (1 < nslab) {
        if (A_KC) stage_mk(SA + SAF, Ab + astep, lda, tid);
        else      stage_km(SA + SAF, Ab + astep, lda, tid);
        if (B_NC) stage_km(SB + SBF, Bb + bstep, ldb, tid);
        else      stage_mk(SB + SBF, Bb + bstep, ldb, tid);
        asm volatile("cp.async.commit_group;");
    }

    float acc[4][8][4];
    #pragma unroll
    for (int a = 0; a < 4; a++)
        #pragma unroll
        for (int b = 0; b < 8; b++)
            #pragma unroll
            for (int c = 0; c < 4; c++) acc[a][b][c] = 0.f;

    int buf = 0;
    for (int s = 0; s < nslab; s++) {
        // ensure slab s is resident; keep slab s+1 in flight when possible
        if (s + 1 < nslab) asm volatile("cp.async.wait_group 1;");
        else               asm volatile("cp.async.wait_group 0;");
        __syncthreads();

        if (s + 2 < nslab) {
            const int nb = (buf + 2 >= NSTG) ? (buf + 2 - NSTG) : (buf + 2);
            const float* As = Ab + (size_t)(s + 2) * astep;
            const float* Bs = Bb + (size_t)(s + 2) * bstep;
            if (A_KC) stage_mk(SA + nb * SAF, As, lda, tid);
            else      stage_km(SA + nb * SAF, As, lda, tid);
            if (B_NC) stage_km(SB + nb * SBF, Bs, ldb, tid);
            else      stage_mk(SB + nb * SBF, Bs, ldb, tid);
            asm volatile("cp.async.commit_group;");
        }

        const float* sa = SA + buf * SAF;
        const float* sb = SB + buf * SBF;
        #pragma unroll
        for (int kc = 0; kc < BK; kc += 8) {
            const int ka = kc + tig, kb = kc + tig + 4;
            unsigned af[4][4], bf[8][2];
            #pragma unroll
            for (int mi = 0; mi < 4; mi++) {
                const int m = wm + mi * 16 + grp;
                if (A_KC) {
                    af[mi][0] = ubits(sa[m * MKP + ka]);
                    af[mi][1] = ubits(sa[(m + 8) * MKP + ka]);
                    af[mi][2] = ubits(sa[m * MKP + kb]);
                    af[mi][3] = ubits(sa[(m + 8) * MKP + kb]);
                } else {
                    af[mi][0] = ubits(sa[ka * KMP + m]);
                    af[mi][1] = ubits(sa[ka * KMP + m + 8]);
                    af[mi][2] = ubits(sa[kb * KMP + m]);
                    af[mi][3] = ubits(sa[kb * KMP + m + 8]);
                }
            }
            #pragma unroll
            for (int nj = 0; nj < 8; nj++) {
                const int n = wn + nj * 8 + grp;
                if (B_NC) {
                    bf[nj][0] = ubits(sb[ka * KMP + n]);
                    bf[nj][1] = ubits(sb[kb * KMP + n]);
                } else {
                    bf[nj][0] = ubits(sb[n * MKP + ka]);
                    bf[nj][1] = ubits(sb[n * MKP + kb]);
                }
            }
            #pragma unroll
            for (int mi = 0; mi < 4; mi++)
                #pragma unroll
                for (int nj = 0; nj < 8; nj++) {
                    asm volatile(
                        "mma.sync.aligned.m16n8k8.row.col.f32.tf32.tf32.f32 "
                        "{%0,%1,%2,%3}, {%4,%5,%6,%7}, {%8,%9}, {%0,%1,%2,%3};"
                        : "+f"(acc[mi][nj][0]), "+f"(acc[mi][nj][1]),
                          "+f"(acc[mi][nj][2]), "+f"(acc[mi][nj][3])
                        : "r"(af[mi][0]), "r"(af[mi][1]),
                          "r"(af[mi][2]), "r"(af[mi][3]),
                          "r"(bf[nj][0]), "r"(bf[nj][1]));
                }
        }
        buf = (buf + 1 >= NSTG) ? 0 : buf + 1;
    }

    // ---- epilogue
    float inv[8][2];
    if (COLSCALE) {
        #pragma unroll
        for (int nj = 0; nj < 8; nj++) {
            const int n = n0 + wn + nj * 8 + (tig << 1);
            inv[nj][0] = 1.f / rsum[n];
            inv[nj][1] = 1.f / rsum[n + 1];
        }
    }
    float rsA[4], rsB[4];
    #pragma unroll
    for (int mi = 0; mi < 4; mi++) { rsA[mi] = 0.f; rsB[mi] = 0.f; }

    #pragma unroll
    for (int mi = 0; mi < 4; mi++) {
        const int mA = m0 + wm + mi * 16 + grp;
        const int mB = mA + 8;
        const float bvA = bias ? bias[mA] : 0.f;
        const float bvB = bias ? bias[mB] : 0.f;
        #pragma unroll
        for (int nj = 0; nj < 8; nj++) {
            const int n = n0 + wn + nj * 8 + (tig << 1);
            float2 o0, o1;
            o0.x = acc[mi][nj][0] * scale + bvA;
            o0.y = acc[mi][nj][1] * scale + bvA;
            o1.x = acc[mi][nj][2] * scale + bvB;
            o1.y = acc[mi][nj][3] * scale + bvB;
            if (DO_EXP) {
                o0.x = __expf(o0.x); o0.y = __expf(o0.y);
                o1.x = __expf(o1.x); o1.y = __expf(o1.y);
                rsA[mi] += o0.x + o0.y;
                rsB[mi] += o1.x + o1.y;
            }
            if (COLSCALE) {
                o0.x *= inv[nj][0]; o0.y *= inv[nj][1];
                o1.x *= inv[nj][0]; o1.y *= inv[nj][1];
            }
            if (resid) {
                float2 r0 = *(const float2*)&resid[(size_t)mA * ldc + n];
                float2 r1 = *(const float2*)&resid[(size_t)mB * ldc + n];
                o0.x += r0.x; o0.y += r0.y;
                o1.x += r1.x; o1.y += r1.y;
            }
            *(float2*)&Cm[(size_t)mA * ldc + n] = o0;
            *(float2*)&Cm[(size_t)mB * ldc + n] = o1;
        }
    }
    if (DO_EXP) {
        #pragma unroll
        for (int mi = 0; mi < 4; mi++) {
            float a = rsA[mi], b = rsB[mi];
            a += __shfl_xor_sync(0xFFFFFFFFu, a, 1);
            a += __shfl_xor_sync(0xFFFFFFFFu, a, 2);
            b += __shfl_xor_sync(0xFFFFFFFFu, b, 1);
            b += __shfl_xor_sync(0xFFFFFFFFu, b, 2);
            if (tig == 0) {
                const int mA = m0 + wm + mi * 16 + grp;
                atomicAdd(&rsum[mA], a);
                atomicAdd(&rsum[mA + 8], b);
            }
        }
    }
}

template<bool A_KC, bool B_NC, bool DO_EXP, bool COLSCALE>
__global__ __launch_bounds__(GT, 2)
void gemm_tc(const float* __restrict__ A,  size_t sAb,
             const float* __restrict__ Bm, size_t sBb,
             float* __restrict__ Cm,       size_t sCb,
             const float* __restrict__ bias,
             const float* __restrict__ resid, size_t sRb,
             float* rsum,
             int K, int lda, int ldb, int ldc, float scale)
{
    extern __shared__ float dyn[];
    const int bz = blockIdx.z;
    gemm_body<A_KC, B_NC, DO_EXP, COLSCALE>(
        dyn,
        A + sAb * bz, Bm + sBb * bz, Cm + sCb * bz,
        bias, resid ? resid + sRb * bz : nullptr,
        rsum ? rsum + (size_t)NTOK * bz : nullptr,
        K, lda, ldb, ldc, scale,
        blockIdx.y * 128, blockIdx.x * 128);
}

struct QKVArgs {
    const float* w[3];
    const float* b[3];
    float*       o[3];
};

__global__ __launch_bounds__(GT, 2)
void qkv_tc(QKVArgs args, const float* __restrict__ h)
{
    extern __shared__ float dyn[];
    const int pj = blockIdx.z / BATCH;
    const int bz = blockIdx.z % BATCH;
    const size_t sCN = (size_t)CH * NTOK;
    gemm_body<true, true, false, false>(
        dyn,
        args.w[pj], h + sCN * bz, args.o[pj] + sCN * bz,
        args.b[pj], nullptr, nullptr,
        CH, CH, NTOK, NTOK, 1.f,
        blockIdx.y * 128, blockIdx.x * 128);
}

// dynamic smem byte sizes per instantiation
static inline int smem_bytes(bool a_kc, bool b_nc)
{
    const int saf = a_kc ? 128 * MKP : 16 * KMP;
    const int sbf = b_nc ? 16 * KMP : 128 * MKP;
    return NSTG * (saf + sbf) * 4;
}

// ---------------- launcher ----------------
extern "C" void kernel_launch(void* const* d_in, const int* in_sizes, int n_in,
                              void* d_out, int out_size)
{
    const float* x     = (const float*)d_in[0];
    const float* gamma = (const float*)d_in[1];
    const float* beta  = (const float*)d_in[2];
    const float* wq    = (const float*)d_in[3];
    const float* bq    = (const float*)d_in[4];
    const float* wk    = (const float*)d_in[5];
    const float* bk    = (const float*)d_in[6];
    const float* wv    = (const float*)d_in[7];
    const float* bv    = (const float*)d_in[8];
    const float* wo    = (const float*)d_in[9];
    const float* bo    = (const float*)d_in[10];
    float* out = (float*)d_out;

    float *h, *q, *k, *v, *ao, *s, *rsum;
    cudaGetSymbolAddress((void**)&h,    g_h);
    cudaGetSymbolAddress((void**)&q,    g_q);
    cudaGetSymbolAddress((void**)&k,    g_k);
    cudaGetSymbolAddress((void**)&v,    g_v);
    cudaGetSymbolAddress((void**)&ao,   g_ao);
    cudaGetSymbolAddress((void**)&s,    g_s);
    cudaGetSymbolAddress((void**)&rsum, g_rsum);

    const size_t sCN = (size_t)CH * NTOK;
    const size_t sNN = (size_t)NTOK * NTOK;
    const float attn_scale = 0.044194173824159216f;   // 512^-0.5

    const int smQKV   = smem_bytes(true,  true);
    const int smScore = smem_bytes(false, true);
    const int smAV    = smem_bytes(true,  false);

    // raise dynamic smem limits (attribute set, not an allocation)
    static bool attr_done = false;
    if (!attr_done) {
        cudaFuncSetAttribute(qkv_tc, cudaFuncAttributeMaxDynamicSharedMemorySize, smQKV);
        cudaFuncSetAttribute(gemm_tc<false, true, true, false>,
                             cudaFuncAttributeMaxDynamicSharedMemorySize, smScore);
        cudaFuncSetAttribute(gemm_tc<true, false, false, true>,
                             cudaFuncAttributeMaxDynamicSharedMemorySize, smAV);
        cudaFuncSetAttribute(gemm_tc<true, true, false, false>,
                             cudaFuncAttributeMaxDynamicSharedMemorySize, smQKV);
        attr_done = true;
    }

    // 1) GroupNorm -> g_h  (also zeroes g_rsum)
    gn_kernel<<<BATCH * GROUPS, 256>>>(x, gamma, beta);

    // 2) fused Q/K/V projections
    QKVArgs qa;
    qa.w[0] = wq; qa.w[1] = wk; qa.w[2] = wv;
    qa.b[0] = bq; qa.b[1] = bk; qa.b[2] = bv;
    qa.o[0] = q;  qa.o[1] = k;  qa.o[2] = v;
    dim3 gQKV(NTOK / 128, CH / 128, 3 * BATCH);
    qkv_tc<<<gQKV, GT, smQKV>>>(qa, h);

    // 3) exp-scores = exp(scale * Q^T K), accumulate rowsums
    dim3 gScore(NTOK / 128, NTOK / 128, BATCH);
    gemm_tc<false, true, true, false><<<gScore, GT, smScore>>>(
        q, sCN, k, sCN, s, sNN,
        (const float*)nullptr, (const float*)nullptr, 0, rsum,
        CH, NTOK, NTOK, NTOK, attn_scale);

    // 4) ao = (V * expS^T) / rowsum[n]
    dim3 gAV(NTOK / 128, CH / 128, BATCH);
    gemm_tc<true, false, false, true><<<gAV, GT, smAV>>>(
        v, sCN, s, sNN, ao, sCN,
        (const float*)nullptr, (const float*)nullptr, 0, rsum,
        NTOK, NTOK, NTOK, NTOK, 1.f);

    // 5) out = x + Wo * ao + bo
    dim3 gProj(NTOK / 128, CH / 128, BATCH);
    gemm_tc<true, true, false, false><<<gProj, GT, smQKV>>>(
        wo, 0, ao, sCN, out, sCN, bo,
        x, sCN, (float*)nullptr,
        CH, CH, NTOK, NTOK, 1.f);
}

// round 11
// speedup vs baseline: 1.9010x; 1.0123x over previous
#include <cuda_runtime.h>
#include <math.h>

#define BATCH  2
#define CH     512
#define NTOK   4096
#define GROUPS 32
#define CPG    16
#define EPS    1e-6f

#define BK     32
#define KMP    136    // k-major smem pitch (floats): [k][m], m contiguous
#define MKP    36     // row-major smem pitch: [row][k], k contiguous (32+4 pad)
#define GT     128    // gemm block threads (4 warps, 2x2 warp grid, 64x64 warp tiles)
#define NSTG   3      // pipeline stages

// ---------------- scratch ----------------
__device__ float g_h [(size_t)BATCH * CH * NTOK];
__device__ float g_q [(size_t)BATCH * CH * NTOK];
__device__ float g_k [(size_t)BATCH * CH * NTOK];
__device__ float g_v [(size_t)BATCH * CH * NTOK];
__device__ float g_ao[(size_t)BATCH * CH * NTOK];
__device__ float g_s [(size_t)BATCH * NTOK * NTOK];
__device__ float g_rsum[(size_t)BATCH * NTOK];

// ---------------- GroupNorm (+ rsum zeroing) ----------------
__global__ void gn_kernel(const float* __restrict__ x,
                          const float* __restrict__ gamma,
                          const float* __restrict__ beta)
{
    const int gid = blockIdx.x * blockDim.x + threadIdx.x;
    if (gid < BATCH * NTOK) g_rsum[gid] = 0.f;

    const int bg = blockIdx.x;
    const int b = bg / GROUPS, g = bg % GROUPS;
    const size_t base = ((size_t)b * CH + (size_t)g * CPG) * NTOK;
    const float* xp = x + base;
    float* hp = g_h + base;
    const int M = CPG * NTOK;

    float s = 0.f, s2 = 0.f;
    for (int i = threadIdx.x * 4; i < M; i += blockDim.x * 4) {
        float4 v = *(const float4*)&xp[i];
        s  += v.x + v.y + v.z + v.w;
        s2 += v.x*v.x + v.y*v.y + v.z*v.z + v.w*v.w;
    }
    __shared__ float shs[8], shs2[8], shbc[2];
    #pragma unroll
    for (int o = 16; o; o >>= 1) {
        s  += __shfl_xor_sync(0xFFFFFFFFu, s,  o);
        s2 += __shfl_xor_sync(0xFFFFFFFFu, s2, o);
    }
    const int wid = threadIdx.x >> 5, lane = threadIdx.x & 31;
    if (!lane) { shs[wid] = s; shs2[wid] = s2; }
    __syncthreads();
    if (threadIdx.x == 0) {
        float ts = 0.f, ts2 = 0.f;
        #pragma unroll
        for (int i = 0; i < 8; i++) { ts += shs[i]; ts2 += shs2[i]; }
        const float mean = ts / (float)M;
        const float var  = ts2 / (float)M - mean * mean;
        shbc[0] = mean;
        shbc[1] = rsqrtf(var + EPS);
    }
    __syncthreads();
    const float mean = shbc[0], rstd = shbc[1];
    for (int i = threadIdx.x * 4; i < M; i += blockDim.x * 4) {
        const int c = g * CPG + (i >> 12);
        const float ga = gamma[c] * rstd;
        const float be = beta[c] - mean * ga;
        float4 v = *(const float4*)&xp[i];
        float4 o;
        o.x = v.x * ga + be; o.y = v.y * ga + be;
        o.z = v.z * ga + be; o.w = v.w * ga + be;
        *(float4*)&hp[i] = o;
    }
}

// ---------------- cp.async staging ----------------
__device__ __forceinline__ void cpa16(float* dst, const float* src)
{
    unsigned s = (unsigned)__cvta_generic_to_shared(dst);
    asm volatile("cp.async.cg.shared.global [%0], [%1], 16;" :: "r"(s), "l"(src));
}

// KM tile: 32 k-rows x 128 cols -> smem[k*KMP + m]   (1024 16B chunks)
__device__ __forceinline__ void stage_km(float* dst, const float* src, int ld, int tid)
{
    #pragma unroll
    for (int i = 0; i < 8; i++) {
        const int c = tid + (i << 7);
        const int k = c >> 5, m4 = (c & 31) << 2;
        cpa16(dst + k * KMP + m4, src + (size_t)k * ld + m4);
    }
}
// MK tile: 128 rows x 32 k -> smem[row*MKP + k]   (1024 16B chunks)
__device__ __forceinline__ void stage_mk(float* dst, const float* src, int ld, int tid)
{
    #pragma unroll
    for (int i = 0; i < 8; i++) {
        const int c = tid + (i << 7);
        const int row = c >> 3, k4 = (c & 7) << 2;
        cpa16(dst + row * MKP + k4, src + (size_t)row * ld + k4);
    }
}

__device__ __forceinline__ unsigned ubits(float f) { return __float_as_uint(f); }

// ---------------- tf32 tensor-core GEMM core ----------------
// C[m,n] = scale * sum_k A(m,k)*B(k,n) (+bias[m]) (+resid) [exp + rowsum] [/ colscale[n]]
// 3-stage cp.async ring in dynamic smem; 4 warps, 64x64 warp tiles; BK=32.
template<bool A_KC, bool B_NC, bool DO_EXP, bool COLSCALE>
__device__ __forceinline__
void gemm_body(float* __restrict__ dyn,
               const float* __restrict__ A,
               const float* __restrict__ Bm,
               float* __restrict__ Cm,
               const float* __restrict__ bias,
               const float* __restrict__ resid,
               float* __restrict__ rsum,
               int K, int lda, int ldb, int ldc, float scale,
               int m0, int n0)
{
    constexpr int SAF = A_KC ? 128 * MKP : BK * KMP;
    constexpr int SBF = B_NC ? BK * KMP : 128 * MKP;
    float* SA = dyn;                  // [NSTG][SAF]
    float* SB = dyn + NSTG * SAF;     // [NSTG][SBF]

    const int tid = threadIdx.x;
    const int warp = tid >> 5, lane = tid & 31;
    const int wm = (warp >> 1) * 64;    // 0 or 64
    const int wn = (warp & 1) * 64;     // 0 or 64
    const int grp = lane >> 2;
    const int tig = lane & 3;

    const float* Ab = A_KC ? (A + (size_t)m0 * lda) : (A + m0);
    const float* Bb = B_NC ? (Bm + n0) : (Bm + (size_t)n0 * ldb);
    const size_t astep = A_KC ? BK : (size_t)BK * lda;
    const size_t bstep = B_NC ? (size_t)BK * ldb : BK;

    const int nslab = K / BK;

    // prologue: issue slabs 0 and 1
    if (A_KC) stage_mk(SA, Ab, lda, tid); else stage_km(SA, Ab, lda, tid);
    if (B_NC) stage_km(SB, Bb, ldb, tid); else stage_mk(SB, Bb, ldb, tid);
    asm volatile("cp.async.commit_group;");
    if (1 < nslab) {
        if (A_KC) stage_mk(SA + SAF, Ab + astep, lda, tid);
        else      stage_km(SA + SAF, Ab + astep, lda, tid);
        if (B_NC) stage_km(SB + SBF, Bb + bstep, ldb, tid);
        else      stage_mk(SB + SBF, Bb + bstep, ldb, tid);
        asm volatile("cp.async.commit_group;");
    }

    float acc[4][8][4];
    #pragma unroll
    for (int a = 0; a < 4; a++)
        #pragma unroll
        for (int b = 0; b < 8; b++)
            #pragma unroll
            for (int c = 0; c < 4; c++) acc[a][b][c] = 0.f;

    int buf = 0;
    for (int s = 0; s < nslab; s++) {
        if (s + 1 < nslab) asm volatile("cp.async.wait_group 1;");
        else               asm volatile("cp.async.wait_group 0;");
        __syncthreads();

        if (s + 2 < nslab) {
            const int nb = (buf + 2 >= NSTG) ? (buf + 2 - NSTG) : (buf + 2);
            const float* As = Ab + (size_t)(s + 2) * astep;
            const float* Bs = Bb + (size_t)(s + 2) * bstep;
            if (A_KC) stage_mk(SA + nb * SAF, As, lda, tid);
            else      stage_km(SA + nb * SAF, As, lda, tid);
            if (B_NC) stage_km(SB + nb * SBF, Bs, ldb, tid);
            else      stage_mk(SB + nb * SBF, Bs, ldb, tid);
            asm volatile("cp.async.commit_group;");
        }

        const float* sa = SA + buf * SAF;
        const float* sb = SB + buf * SBF;
        #pragma unroll
        for (int kc = 0; kc < BK; kc += 8) {
            const int ka = kc + tig, kb = kc + tig + 4;
            unsigned af[4][4], bf[8][2];
            #pragma unroll
            for (int mi = 0; mi < 4; mi++) {
                const int m = wm + mi * 16 + grp;
                if (A_KC) {
                    af[mi][0] = ubits(sa[m * MKP + ka]);
                    af[mi][1] = ubits(sa[(m + 8) * MKP + ka]);
                    af[mi][2] = ubits(sa[m * MKP + kb]);
                    af[mi][3] = ubits(sa[(m + 8) * MKP + kb]);
                } else {
                    af[mi][0] = ubits(sa[ka * KMP + m]);
                    af[mi][1] = ubits(sa[ka * KMP + m + 8]);
                    af[mi][2] = ubits(sa[kb * KMP + m]);
                    af[mi][3] = ubits(sa[kb * KMP + m + 8]);
                }
            }
            #pragma unroll
            for (int nj = 0; nj < 8; nj++) {
                const int n = wn + nj * 8 + grp;
                if (B_NC) {
                    bf[nj][0] = ubits(sb[ka * KMP + n]);
                    bf[nj][1] = ubits(sb[kb * KMP + n]);
                } else {
                    bf[nj][0] = ubits(sb[n * MKP + ka]);
                    bf[nj][1] = ubits(sb[n * MKP + kb]);
                }
            }
            #pragma unroll
            for (int mi = 0; mi < 4; mi++)
                #pragma unroll
                for (int nj = 0; nj < 8; nj++) {
                    asm volatile(
                        "mma.sync.aligned.m16n8k8.row.col.f32.tf32.tf32.f32 "
                        "{%0,%1,%2,%3}, {%4,%5,%6,%7}, {%8,%9}, {%0,%1,%2,%3};"
                        : "+f"(acc[mi][nj][0]), "+f"(acc[mi][nj][1]),
                          "+f"(acc[mi][nj][2]), "+f"(acc[mi][nj][3])
                        : "r"(af[mi][0]), "r"(af[mi][1]),
                          "r"(af[mi][2]), "r"(af[mi][3]),
                          "r"(bf[nj][0]), "r"(bf[nj][1]));
                }
        }
        buf = (buf + 1 >= NSTG) ? 0 : buf + 1;
    }

    // ---- epilogue
    float inv[8][2];
    if (COLSCALE) {
        #pragma unroll
        for (int nj = 0; nj < 8; nj++) {
            const int n = n0 + wn + nj * 8 + (tig << 1);
            inv[nj][0] = 1.f / rsum[n];
            inv[nj][1] = 1.f / rsum[n + 1];
        }
    }
    float rsA[4], rsB[4];
    #pragma unroll
    for (int mi = 0; mi < 4; mi++) { rsA[mi] = 0.f; rsB[mi] = 0.f; }

    #pragma unroll
    for (int mi = 0; mi < 4; mi++) {
        const int mA = m0 + wm + mi * 16 + grp;
        const int mB = mA + 8;
        const float bvA = bias ? bias[mA] : 0.f;
        const float bvB = bias ? bias[mB] : 0.f;
        #pragma unroll
        for (int nj = 0; nj < 8; nj++) {
            const int n = n0 + wn + nj * 8 + (tig << 1);
            float2 o0, o1;
            o0.x = acc[mi][nj][0] * scale + bvA;
            o0.y = acc[mi][nj][1] * scale + bvA;
            o1.x = acc[mi][nj][2] * scale + bvB;
            o1.y = acc[mi][nj][3] * scale + bvB;
            if (DO_EXP) {
                o0.x = __expf(o0.x); o0.y = __expf(o0.y);
                o1.x = __expf(o1.x); o1.y = __expf(o1.y);
                rsA[mi] += o0.x + o0.y;
                rsB[mi] += o1.x + o1.y;
            }
            if (COLSCALE) {
                o0.x *= inv[nj][0]; o0.y *= inv[nj][1];
                o1.x *= inv[nj][0]; o1.y *= inv[nj][1];
            }
            if (resid) {
                float2 r0 = *(const float2*)&resid[(size_t)mA * ldc + n];
                float2 r1 = *(const float2*)&resid[(size_t)mB * ldc + n];
                o0.x += r0.x; o0.y += r0.y;
                o1.x += r1.x; o1.y += r1.y;
            }
            *(float2*)&Cm[(size_t)mA * ldc + n] = o0;
            *(float2*)&Cm[(size_t)mB * ldc + n] = o1;
        }
    }
    if (DO_EXP) {
        #pragma unroll
        for (int mi = 0; mi < 4; mi++) {
            float a = rsA[mi], b = rsB[mi];
            a += __shfl_xor_sync(0xFFFFFFFFu, a, 1);
            a += __shfl_xor_sync(0xFFFFFFFFu, a, 2);
            b += __shfl_xor_sync(0xFFFFFFFFu, b, 1);
            b += __shfl_xor_sync(0xFFFFFFFFu, b, 2);
            if (tig == 0) {
                const int mA = m0 + wm + mi * 16 + grp;
                atomicAdd(&rsum[mA], a);
                atomicAdd(&rsum[mA + 8], b);
            }
        }
    }
}

template<bool A_KC, bool B_NC, bool DO_EXP, bool COLSCALE>
__global__ __launch_bounds__(GT, 2)
void gemm_tc(const float* __restrict__ A,  size_t sAb,
             const float* __restrict__ Bm, size_t sBb,
             float* __restrict__ Cm,       size_t sCb,
             const float* __restrict__ bias,
             const float* __restrict__ resid, size_t sRb,
             float* rsum,
             int K, int lda, int ldb, int ldc, float scale)
{
    extern __shared__ float dyn[];
    const int bz = blockIdx.z;
    gemm_body<A_KC, B_NC, DO_EXP, COLSCALE>(
        dyn,
        A + sAb * bz, Bm + sBb * bz, Cm + sCb * bz,
        bias, resid ? resid + sRb * bz : nullptr,
        rsum ? rsum + (size_t)NTOK * bz : nullptr,
        K, lda, ldb, ldc, scale,
        blockIdx.y * 128, blockIdx.x * 128);
}

struct QKVArgs {
    const float* w[3];
    const float* b[3];
    float*       o[3];
};

__global__ __launch_bounds__(GT, 2)
void qkv_tc(QKVArgs args, const float* __restrict__ h)
{
    extern __shared__ float dyn[];
    const int pj = blockIdx.z / BATCH;
    const int bz = blockIdx.z % BATCH;
    const size_t sCN = (size_t)CH * NTOK;
    gemm_body<true, true, false, false>(
        dyn,
        args.w[pj], h + sCN * bz, args.o[pj] + sCN * bz,
        args.b[pj], nullptr, nullptr,
        CH, CH, NTOK, NTOK, 1.f,
        blockIdx.y * 128, blockIdx.x * 128);
}

// dynamic smem byte sizes per instantiation
static inline int smem_bytes(bool a_kc, bool b_nc)
{
    const int saf = a_kc ? 128 * MKP : BK * KMP;
    const int sbf = b_nc ? BK * KMP : 128 * MKP;
    return NSTG * (saf + sbf) * 4;
}

// ---------------- launcher ----------------
extern "C" void kernel_launch(void* const* d_in, const int* in_sizes, int n_in,
                              void* d_out, int out_size)
{
    const float* x     = (const float*)d_in[0];
    const float* gamma = (const float*)d_in[1];
    const float* beta  = (const float*)d_in[2];
    const float* wq    = (const float*)d_in[3];
    const float* bq    = (const float*)d_in[4];
    const float* wk    = (const float*)d_in[5];
    const float* bk    = (const float*)d_in[6];
    const float* wv    = (const float*)d_in[7];
    const float* bv    = (const float*)d_in[8];
    const float* wo    = (const float*)d_in[9];
    const float* bo    = (const float*)d_in[10];
    float* out = (float*)d_out;

    float *h, *q, *k, *v, *ao, *s, *rsum;
    cudaGetSymbolAddress((void**)&h,    g_h);
    cudaGetSymbolAddress((void**)&q,    g_q);
    cudaGetSymbolAddress((void**)&k,    g_k);
    cudaGetSymbolAddress((void**)&v,    g_v);
    cudaGetSymbolAddress((void**)&ao,   g_ao);
    cudaGetSymbolAddress((void**)&s,    g_s);
    cudaGetSymbolAddress((void**)&rsum, g_rsum);

    const size_t sCN = (size_t)CH * NTOK;
    const size_t sNN = (size_t)NTOK * NTOK;
    const float attn_scale = 0.044194173824159216f;   // 512^-0.5

    const int smQKV   = smem_bytes(true,  true);
    const int smScore = smem_bytes(false, true);
    const int smAV    = smem_bytes(true,  false);

    static bool attr_done = false;
    if (!attr_done) {
        cudaFuncSetAttribute(qkv_tc, cudaFuncAttributeMaxDynamicSharedMemorySize, smQKV);
        cudaFuncSetAttribute(gemm_tc<false, true, true, false>,
                             cudaFuncAttributeMaxDynamicSharedMemorySize, smScore);
        cudaFuncSetAttribute(gemm_tc<true, false, false, true>,
                             cudaFuncAttributeMaxDynamicSharedMemorySize, smAV);
        cudaFuncSetAttribute(gemm_tc<true, true, false, false>,
                             cudaFuncAttributeMaxDynamicSharedMemorySize, smQKV);
        attr_done = true;
    }

    // 1) GroupNorm -> g_h  (also zeroes g_rsum)
    gn_kernel<<<BATCH * GROUPS, 256>>>(x, gamma, beta);

    // 2) fused Q/K/V projections
    QKVArgs qa;
    qa.w[0] = wq; qa.w[1] = wk; qa.w[2] = wv;
    qa.b[0] = bq; qa.b[1] = bk; qa.b[2] = bv;
    qa.o[0] = q;  qa.o[1] = k;  qa.o[2] = v;
    dim3 gQKV(NTOK / 128, CH / 128, 3 * BATCH);
    qkv_tc<<<gQKV, GT, smQKV>>>(qa, h);

    // 3) exp-scores = exp(scale * Q^T K), accumulate rowsums
    dim3 gScore(NTOK / 128, NTOK / 128, BATCH);
    gemm_tc<false, true, true, false><<<gScore, GT, smScore>>>(
        q, sCN, k, sCN, s, sNN,
        (const float*)nullptr, (const float*)nullptr, 0, rsum,
        CH, NTOK, NTOK, NTOK, attn_scale);

    // 4) ao = (V * expS^T) / rowsum[n]
    dim3 gAV(NTOK / 128, CH / 128, BATCH);
    gemm_tc<true, false, false, true><<<gAV, GT, smAV>>>(
        v, sCN, s, sNN, ao, sCN,
        (const float*)nullptr, (const float*)nullptr, 0, rsum,
        NTOK, NTOK, NTOK, NTOK, 1.f);

    // 5) out = x + Wo * ao + bo
    dim3 gProj(NTOK / 128, CH / 128, BATCH);
    gemm_tc<true, true, false, false><<<gProj, GT, smQKV>>>(
        wo, 0, ao, sCN, out, sCN, bo,
        x, sCN, (float*)nullptr,
        CH, CH, NTOK, NTOK, 1.f);
}

// round 12
// speedup vs baseline: 2.6630x; 1.4009x over previous
#include <cuda_runtime.h>
#include <cuda_fp16.h>
#include <math.h>

#define BATCH  2
#define CH     512
#define NTOK   4096
#define GROUPS 32
#define CPG    16
#define EPS    1e-6f

#define BK     32
#define KMP    136    // tf32 k-major smem pitch (floats)
#define MKP    36     // tf32 row-major smem pitch (floats)
#define MKPH   40     // fp16 row-major smem pitch (halfs): 20*row+tig covers 32 banks
#define GT     128    // 4 warps, 2x2 warp grid, 64x64 warp tiles
#define NSTG   3

// ---------------- scratch ----------------
__device__ float  g_h  [(size_t)BATCH * CH * NTOK];   // groupnorm out [b][c][n]
__device__ __half g_qt [(size_t)BATCH * NTOK * CH];   // q^T [b][nq][c]
__device__ __half g_kt [(size_t)BATCH * NTOK * CH];   // k^T [b][nk][c]
__device__ __half g_vh [(size_t)BATCH * CH * NTOK];   // v   [b][c][nk]
__device__ __half g_sh [(size_t)BATCH * NTOK * NTOK]; // exp-scores [b][nq][nk]
__device__ float  g_ao [(size_t)BATCH * CH * NTOK];   // attn out [b][c][nq]
__device__ float  g_rsum[(size_t)BATCH * NTOK];

// ---------------- GroupNorm (+ rsum zeroing) ----------------
__global__ void gn_kernel(const float* __restrict__ x,
                          const float* __restrict__ gamma,
                          const float* __restrict__ beta)
{
    const int gid = blockIdx.x * blockDim.x + threadIdx.x;
    if (gid < BATCH * NTOK) g_rsum[gid] = 0.f;

    const int bg = blockIdx.x;
    const int b = bg / GROUPS, g = bg % GROUPS;
    const size_t base = ((size_t)b * CH + (size_t)g * CPG) * NTOK;
    const float* xp = x + base;
    float* hp = g_h + base;
    const int M = CPG * NTOK;

    float s = 0.f, s2 = 0.f;
    for (int i = threadIdx.x * 4; i < M; i += blockDim.x * 4) {
        float4 v = *(const float4*)&xp[i];
        s  += v.x + v.y + v.z + v.w;
        s2 += v.x*v.x + v.y*v.y + v.z*v.z + v.w*v.w;
    }
    __shared__ float shs[8], shs2[8], shbc[2];
    #pragma unroll
    for (int o = 16; o; o >>= 1) {
        s  += __shfl_xor_sync(0xFFFFFFFFu, s,  o);
        s2 += __shfl_xor_sync(0xFFFFFFFFu, s2, o);
    }
    const int wid = threadIdx.x >> 5, lane = threadIdx.x & 31;
    if (!lane) { shs[wid] = s; shs2[wid] = s2; }
    __syncthreads();
    if (threadIdx.x == 0) {
        float ts = 0.f, ts2 = 0.f;
        #pragma unroll
        for (int i = 0; i < 8; i++) { ts += shs[i]; ts2 += shs2[i]; }
        const float mean = ts / (float)M;
        const float var  = ts2 / (float)M - mean * mean;
        shbc[0] = mean;
        shbc[1] = rsqrtf(var + EPS);
    }
    __syncthreads();
    const float mean = shbc[0], rstd = shbc[1];
    for (int i = threadIdx.x * 4; i < M; i += blockDim.x * 4) {
        const int c = g * CPG + (i >> 12);
        const float ga = gamma[c] * rstd;
        const float be = beta[c] - mean * ga;
        float4 v = *(const float4*)&xp[i];
        float4 o;
        o.x = v.x * ga + be; o.y = v.y * ga + be;
        o.z = v.z * ga + be; o.w = v.w * ga + be;
        *(float4*)&hp[i] = o;
    }
}

// ---------------- cp.async helpers ----------------
__device__ __forceinline__ void cpa16(float* dst, const float* src)
{
    unsigned s = (unsigned)__cvta_generic_to_shared(dst);
    asm volatile("cp.async.cg.shared.global [%0], [%1], 16;" :: "r"(s), "l"(src));
}
__device__ __forceinline__ void cpa16h(__half* dst, const __half* src)
{
    unsigned s = (unsigned)__cvta_generic_to_shared(dst);
    asm volatile("cp.async.cg.shared.global [%0], [%1], 16;" :: "r"(s), "l"(src));
}

// tf32 KM tile: 32 k-rows x 128 cols -> smem[k*KMP + m]
__device__ __forceinline__ void stage_km(float* dst, const float* src, int ld, int tid)
{
    #pragma unroll
    for (int i = 0; i < 8; i++) {
        const int c = tid + (i << 7);
        const int k = c >> 5, m4 = (c & 31) << 2;
        cpa16(dst + k * KMP + m4, src + (size_t)k * ld + m4);
    }
}
// tf32 MK tile: 128 rows x 32 k -> smem[row*MKP + k]
__device__ __forceinline__ void stage_mk(float* dst, const float* src, int ld, int tid)
{
    #pragma unroll
    for (int i = 0; i < 8; i++) {
        const int c = tid + (i << 7);
        const int row = c >> 3, k4 = (c & 7) << 2;
        cpa16(dst + row * MKP + k4, src + (size_t)row * ld + k4);
    }
}
// fp16 MK tile: 128 rows x 32 halfs -> smem[row*MKPH + k]
__device__ __forceinline__ void stage_h(__half* dst, const __half* src, int ld, int tid)
{
    #pragma unroll
    for (int i = 0; i < 4; i++) {
        const int c = tid + (i << 7);
        const int row = c >> 2, k8 = (c & 3) << 3;
        cpa16h(dst + row * MKPH + k8, src + (size_t)row * ld + k8);
    }
}

__device__ __forceinline__ unsigned ubits(float f) { return __float_as_uint(f); }
__device__ __forceinline__ unsigned ld32s(const __half* p) { return *(const unsigned*)p; }

// ================= fp16 tensor-core GEMM (both operands row-major, k-contig) =================
// C[m,n] = scale * sum_k A[m,k]*B[n,k]  [exp + rowsum[m]] [/ rsum[n]]
// HALF_OUT: write half2; else float2.
template<bool DO_EXP, bool COLSCALE, bool HALF_OUT>
__global__ __launch_bounds__(GT, 2)
void gemm_h(const __half* __restrict__ A,  size_t sAb,
            const __half* __restrict__ Bm, size_t sBb,
            void* __restrict__ Cv,         size_t sCb,
            float* rsum,
            int K, int lda, int ldb, int ldc, float scale)
{
    extern __shared__ __half dynh[];
    constexpr int TF = 128 * MKPH;     // halfs per tile
    __half* SA = dynh;                 // [NSTG][TF]
    __half* SB = dynh + NSTG * TF;

    const int bz = blockIdx.z;
    A  += sAb * bz;
    Bm += sBb * bz;
    char* Cb = (char*)Cv + (HALF_OUT ? sCb * 2 : sCb * 4) * bz;
    if (rsum) rsum += (size_t)NTOK * bz;

    const int tid = threadIdx.x;
    const int warp = tid >> 5, lane = tid & 31;
    const int wm = (warp >> 1) * 64;
    const int wn = (warp & 1) * 64;
    const int grp = lane >> 2;
    const int tig = lane & 3;
    const int m0 = blockIdx.y * 128, n0 = blockIdx.x * 128;

    const __half* At = A + (size_t)m0 * lda;
    const __half* Bt = Bm + (size_t)n0 * ldb;
    const int nslab = K / BK;

    stage_h(SA, At, lda, tid);
    stage_h(SB, Bt, ldb, tid);
    asm volatile("cp.async.commit_group;");
    if (1 < nslab) {
        stage_h(SA + TF, At + BK, lda, tid);
        stage_h(SB + TF, Bt + BK, ldb, tid);
        asm volatile("cp.async.commit_group;");
    }

    float acc[4][8][4];
    #pragma unroll
    for (int a = 0; a < 4; a++)
        #pragma unroll
        for (int b = 0; b < 8; b++)
            #pragma unroll
            for (int c = 0; c < 4; c++) acc[a][b][c] = 0.f;

    int buf = 0;
    for (int s = 0; s < nslab; s++) {
        if (s + 1 < nslab) asm volatile("cp.async.wait_group 1;");
        else               asm volatile("cp.async.wait_group 0;");
        __syncthreads();

        if (s + 2 < nslab) {
            const int nb = (buf + 2 >= NSTG) ? (buf + 2 - NSTG) : (buf + 2);
            stage_h(SA + nb * TF, At + (size_t)(s + 2) * BK, lda, tid);
            stage_h(SB + nb * TF, Bt + (size_t)(s + 2) * BK, ldb, tid);
            asm volatile("cp.async.commit_group;");
        }

        const __half* sa = SA + buf * TF;
        const __half* sb = SB + buf * TF;
        #pragma unroll
        for (int kc = 0; kc < BK; kc += 16) {
            const int k0i = kc + (tig << 1);
            unsigned af[4][4], bf[8][2];
            #pragma unroll
            for (int mi = 0; mi < 4; mi++) {
                const int m = wm + mi * 16 + grp;
                af[mi][0] = ld32s(sa + m * MKPH + k0i);
                af[mi][1] = ld32s(sa + (m + 8) * MKPH + k0i);
                af[mi][2] = ld32s(sa + m * MKPH + k0i + 8);
                af[mi][3] = ld32s(sa + (m + 8) * MKPH + k0i + 8);
            }
            #pragma unroll
            for (int nj = 0; nj < 8; nj++) {
                const int n = wn + nj * 8 + grp;
                bf[nj][0] = ld32s(sb + n * MKPH + k0i);
                bf[nj][1] = ld32s(sb + n * MKPH + k0i + 8);
            }
            #pragma unroll
            for (int mi = 0; mi < 4; mi++)
                #pragma unroll
                for (int nj = 0; nj < 8; nj++) {
                    asm volatile(
                        "mma.sync.aligned.m16n8k16.row.col.f32.f16.f16.f32 "
                        "{%0,%1,%2,%3}, {%4,%5,%6,%7}, {%8,%9}, {%0,%1,%2,%3};"
                        : "+f"(acc[mi][nj][0]), "+f"(acc[mi][nj][1]),
                          "+f"(acc[mi][nj][2]), "+f"(acc[mi][nj][3])
                        : "r"(af[mi][0]), "r"(af[mi][1]),
                          "r"(af[mi][2]), "r"(af[mi][3]),
                          "r"(bf[nj][0]), "r"(bf[nj][1]));
                }
        }
        buf = (buf + 1 >= NSTG) ? 0 : buf + 1;
    }

    // ---- epilogue
    float inv[8][2];
    if (COLSCALE) {
        #pragma unroll
        for (int nj = 0; nj < 8; nj++) {
            const int n = n0 + wn + nj * 8 + (tig << 1);
            inv[nj][0] = 1.f / rsum[n];
            inv[nj][1] = 1.f / rsum[n + 1];
        }
    }
    float rsA[4], rsB[4];
    #pragma unroll
    for (int mi = 0; mi < 4; mi++) { rsA[mi] = 0.f; rsB[mi] = 0.f; }

    #pragma unroll
    for (int mi = 0; mi < 4; mi++) {
        const int mA = m0 + wm + mi * 16 + grp;
        const int mB = mA + 8;
        #pragma unroll
        for (int nj = 0; nj < 8; nj++) {
            const int n = n0 + wn + nj * 8 + (tig << 1);
            float2 o0, o1;
            o0.x = acc[mi][nj][0] * scale;
            o0.y = acc[mi][nj][1] * scale;
            o1.x = acc[mi][nj][2] * scale;
            o1.y = acc[mi][nj][3] * scale;
            if (DO_EXP) {
                o0.x = __expf(o0.x); o0.y = __expf(o0.y);
                o1.x = __expf(o1.x); o1.y = __expf(o1.y);
                rsA[mi] += o0.x + o0.y;
                rsB[mi] += o1.x + o1.y;
            }
            if (COLSCALE) {
                o0.x *= inv[nj][0]; o0.y *= inv[nj][1];
                o1.x *= inv[nj][0]; o1.y *= inv[nj][1];
            }
            if (HALF_OUT) {
                __half* hC = (__half*)Cb;
                *(__half2*)&hC[(size_t)mA * ldc + n] = __floats2half2_rn(o0.x, o0.y);
                *(__half2*)&hC[(size_t)mB * ldc + n] = __floats2half2_rn(o1.x, o1.y);
            } else {
                float* fC = (float*)Cb;
                *(float2*)&fC[(size_t)mA * ldc + n] = o0;
                *(float2*)&fC[(size_t)mB * ldc + n] = o1;
            }
        }
    }
    if (DO_EXP) {
        #pragma unroll
        for (int mi = 0; mi < 4; mi++) {
            float a = rsA[mi], b = rsB[mi];
            a += __shfl_xor_sync(0xFFFFFFFFu, a, 1);
            a += __shfl_xor_sync(0xFFFFFFFFu, a, 2);
            b += __shfl_xor_sync(0xFFFFFFFFu, b, 1);
            b += __shfl_xor_sync(0xFFFFFFFFu, b, 2);
            if (tig == 0) {
                const int mA = m0 + wm + mi * 16 + grp;
                atomicAdd(&rsum[mA], a);
                atomicAdd(&rsum[mA + 8], b);
            }
        }
    }
}

// ================= tf32 GEMM (A row-major mk, B k-major kn) =================
// omode: 0 = fp32 normal (+resid), 1 = half normal, 2 = half transposed
__device__ __forceinline__
void gemm_tf_body(float* __restrict__ dyn,
                  const float* __restrict__ A,
                  const float* __restrict__ Bm,
                  void* __restrict__ Cv,
                  const float* __restrict__ bias,
                  const float* __restrict__ resid,
                  int K, int lda, int ldb, int ldc,
                  int omode, int m0, int n0)
{
    constexpr int SAF = 128 * MKP;
    constexpr int SBF = BK * KMP;
    float* SA = dyn;
    float* SB = dyn + NSTG * SAF;

    const int tid = threadIdx.x;
    const int warp = tid >> 5, lane = tid & 31;
    const int wm = (warp >> 1) * 64;
    const int wn = (warp & 1) * 64;
    const int grp = lane >> 2;
    const int tig = lane & 3;

    const float* Ab = A + (size_t)m0 * lda;
    const float* Bb = Bm + n0;
    const int nslab = K / BK;

    stage_mk(SA, Ab, lda, tid);
    stage_km(SB, Bb, ldb, tid);
    asm volatile("cp.async.commit_group;");
    if (1 < nslab) {
        stage_mk(SA + SAF, Ab + BK, lda, tid);
        stage_km(SB + SBF, Bb + (size_t)BK * ldb, ldb, tid);
        asm volatile("cp.async.commit_group;");
    }

    float acc[4][8][4];
    #pragma unroll
    for (int a = 0; a < 4; a++)
        #pragma unroll
        for (int b = 0; b < 8; b++)
            #pragma unroll
            for (int c = 0; c < 4; c++) acc[a][b][c] = 0.f;

    int buf = 0;
    for (int s = 0; s < nslab; s++) {
        if (s + 1 < nslab) asm volatile("cp.async.wait_group 1;");
        else               asm volatile("cp.async.wait_group 0;");
        __syncthreads();

        if (s + 2 < nslab) {
            const int nb = (buf + 2 >= NSTG) ? (buf + 2 - NSTG) : (buf + 2);
            stage_mk(SA + nb * SAF, Ab + (size_t)(s + 2) * BK, lda, tid);
            stage_km(SB + nb * SBF, Bb + (size_t)(s + 2) * BK * ldb, ldb, tid);
            asm volatile("cp.async.commit_group;");
        }

        const float* sa = SA + buf * SAF;
        const float* sb = SB + buf * SBF;
        #pragma unroll
        for (int kc = 0; kc < BK; kc += 8) {
            const int ka = kc + tig, kb = kc + tig + 4;
            unsigned af[4][4], bf[8][2];
            #pragma unroll
            for (int mi = 0; mi < 4; mi++) {
                const int m = wm + mi * 16 + grp;
                af[mi][0] = ubits(sa[m * MKP + ka]);
                af[mi][1] = ubits(sa[(m + 8) * MKP + ka]);
                af[mi][2] = ubits(sa[m * MKP + kb]);
                af[mi][3] = ubits(sa[(m + 8) * MKP + kb]);
            }
            #pragma unroll
            for (int nj = 0; nj < 8; nj++) {
                const int n = wn + nj * 8 + grp;
                bf[nj][0] = ubits(sb[ka * KMP + n]);
                bf[nj][1] = ubits(sb[kb * KMP + n]);
            }
            #pragma unroll
            for (int mi = 0; mi < 4; mi++)
                #pragma unroll
                for (int nj = 0; nj < 8; nj++) {
                    asm volatile(
                        "mma.sync.aligned.m16n8k8.row.col.f32.tf32.tf32.f32 "
                        "{%0,%1,%2,%3}, {%4,%5,%6,%7}, {%8,%9}, {%0,%1,%2,%3};"
                        : "+f"(acc[mi][nj][0]), "+f"(acc[mi][nj][1]),
                          "+f"(acc[mi][nj][2]), "+f"(acc[mi][nj][3])
                        : "r"(af[mi][0]), "r"(af[mi][1]),
                          "r"(af[mi][2]), "r"(af[mi][3]),
                          "r"(bf[nj][0]), "r"(bf[nj][1]));
                }
        }
        buf = (buf + 1 >= NSTG) ? 0 : buf + 1;
    }

    // ---- epilogue
    #pragma unroll
    for (int mi = 0; mi < 4; mi++) {
        const int mA = m0 + wm + mi * 16 + grp;
        const int mB = mA + 8;
        const float bvA = bias ? bias[mA] : 0.f;
        const float bvB = bias ? bias[mB] : 0.f;
        #pragma unroll
        for (int nj = 0; nj < 8; nj++) {
            const int n = n0 + wn + nj * 8 + (tig << 1);
            float2 o0, o1;
            o0.x = acc[mi][nj][0] + bvA;
            o0.y = acc[mi][nj][1] + bvA;
            o1.x = acc[mi][nj][2] + bvB;
            o1.y = acc[mi][nj][3] + bvB;
            if (omode == 0) {
                float* fC = (float*)Cv;
                if (resid) {
                    float2 r0 = *(const float2*)&resid[(size_t)mA * ldc + n];
                    float2 r1 = *(const float2*)&resid[(size_t)mB * ldc + n];
                    o0.x += r0.x; o0.y += r0.y;
                    o1.x += r1.x; o1.y += r1.y;
                }
                *(float2*)&fC[(size_t)mA * ldc + n] = o0;
                *(float2*)&fC[(size_t)mB * ldc + n] = o1;
            } else if (omode == 1) {
                __half* hC = (__half*)Cv;
                *(__half2*)&hC[(size_t)mA * ldc + n] = __floats2half2_rn(o0.x, o0.y);
                *(__half2*)&hC[(size_t)mB * ldc + n] = __floats2half2_rn(o1.x, o1.y);
            } else {
                __half* hC = (__half*)Cv;
                hC[(size_t)n * ldc + mA]       = __float2half_rn(o0.x);
                hC[(size_t)(n + 1) * ldc + mA] = __float2half_rn(o0.y);
                hC[(size_t)n * ldc + mB]       = __float2half_rn(o1.x);
                hC[(size_t)(n + 1) * ldc + mB] = __float2half_rn(o1.y);
            }
        }
    }
}

struct QKVArgs {
    const float* w[3];
    const float* b[3];
    void*        o[3];
    int          ldc[3];
    int          omode[3];
    size_t       ostride[3];   // per-batch element stride of output
};

__global__ __launch_bounds__(GT, 2)
void qkv_tc(QKVArgs args, const float* __restrict__ h)
{
    extern __shared__ float dynf[];
    const int pj = blockIdx.z / BATCH;
    const int bz = blockIdx.z % BATCH;
    const size_t sCN = (size_t)CH * NTOK;
    void* outp = (args.omode[pj] == 0)
        ? (void*)((float*)args.o[pj] + args.ostride[pj] * bz)
        : (void*)((__half*)args.o[pj] + args.ostride[pj] * bz);
    gemm_tf_body(dynf, args.w[pj], h + sCN * bz, outp,
                 args.b[pj], nullptr,
                 CH, CH, NTOK, args.ldc[pj], args.omode[pj],
                 blockIdx.y * 128, blockIdx.x * 128);
}

__global__ __launch_bounds__(GT, 2)
void wo_tc(const float* __restrict__ wo, const float* __restrict__ ao,
           float* __restrict__ out, const float* __restrict__ bo,
           const float* __restrict__ x)
{
    extern __shared__ float dynf[];
    const int bz = blockIdx.z;
    const size_t sCN = (size_t)CH * NTOK;
    gemm_tf_body(dynf, wo, ao + sCN * bz, out + sCN * bz,
                 bo, x + sCN * bz,
                 CH, CH, NTOK, NTOK, 0,
                 blockIdx.y * 128, blockIdx.x * 128);
}

// ---------------- launcher ----------------
extern "C" void kernel_launch(void* const* d_in, const int* in_sizes, int n_in,
                              void* d_out, int out_size)
{
    const float* x     = (const float*)d_in[0];
    const float* gamma = (const float*)d_in[1];
    const float* beta  = (const float*)d_in[2];
    const float* wq    = (const float*)d_in[3];
    const float* bq    = (const float*)d_in[4];
    const float* wk    = (const float*)d_in[5];
    const float* bk    = (const float*)d_in[6];
    const float* wv    = (const float*)d_in[7];
    const float* bv    = (const float*)d_in[8];
    const float* wo    = (const float*)d_in[9];
    const float* bo    = (const float*)d_in[10];
    float* out = (float*)d_out;

    float *h, *ao, *rsum;
    __half *qt, *kt, *vh, *sh;
    cudaGetSymbolAddress((void**)&h,    g_h);
    cudaGetSymbolAddress((void**)&qt,   g_qt);
    cudaGetSymbolAddress((void**)&kt,   g_kt);
    cudaGetSymbolAddress((void**)&vh,   g_vh);
    cudaGetSymbolAddress((void**)&sh,   g_sh);
    cudaGetSymbolAddress((void**)&ao,   g_ao);
    cudaGetSymbolAddress((void**)&rsum, g_rsum);

    const size_t sNC = (size_t)NTOK * CH;
    const size_t sNN = (size_t)NTOK * NTOK;
    const size_t sCN = (size_t)CH * NTOK;
    const float attn_scale = 0.044194173824159216f;   // 512^-0.5

    const int smTF = NSTG * (128 * MKP + BK * KMP) * 4;   // tf32 kernels
    const int smH  = NSTG * 2 * (128 * MKPH) * 2;         // fp16 kernels

    static bool attr_done = false;
    if (!attr_done) {
        cudaFuncSetAttribute(qkv_tc, cudaFuncAttributeMaxDynamicSharedMemorySize, smTF);
        cudaFuncSetAttribute(wo_tc,  cudaFuncAttributeMaxDynamicSharedMemorySize, smTF);
        cudaFuncSetAttribute(gemm_h<true, false, true>,
                             cudaFuncAttributeMaxDynamicSharedMemorySize, smH);
        cudaFuncSetAttribute(gemm_h<false, true, false>,
                             cudaFuncAttributeMaxDynamicSharedMemorySize, smH);
        attr_done = true;
    }

    // 1) GroupNorm -> g_h  (also zeroes g_rsum)
    gn_kernel<<<BATCH * GROUPS, 256>>>(x, gamma, beta);

    // 2) Q/K/V projections (tf32): q^T, k^T (half transposed), v (half)
    QKVArgs qa;
    qa.w[0] = wq; qa.w[1] = wk; qa.w[2] = wv;
    qa.b[0] = bq; qa.b[1] = bk; qa.b[2] = bv;
    qa.o[0] = qt; qa.o[1] = kt; qa.o[2] = vh;
    qa.ldc[0] = CH; qa.ldc[1] = CH; qa.ldc[2] = NTOK;
    qa.omode[0] = 2; qa.omode[1] = 2; qa.omode[2] = 1;
    qa.ostride[0] = sNC; qa.ostride[1] = sNC; qa.ostride[2] = sCN;
    qkv_tc<<<dim3(NTOK / 128, CH / 128, 3 * BATCH), GT, smTF>>>(qa, h);

    // 3) exp-scores (fp16): s[nq][nk] = exp(scale * q^T·k), rowsum[nq]
    gemm_h<true, false, true><<<dim3(NTOK / 128, NTOK / 128, BATCH), GT, smH>>>(
        qt, sNC, kt, sNC, sh, sNN, rsum,
        CH, CH, CH, NTOK, attn_scale);

    // 4) ao[c][nq] = (v·s^T)/rsum[nq]  (fp16 inputs, fp32 out)
    gemm_h<false, true, false><<<dim3(NTOK / 128, CH / 128, BATCH), GT, smH>>>(
        vh, sCN, sh, sNN, ao, sCN, rsum,
        NTOK, NTOK, NTOK, NTOK, 1.f);

    // 5) out = x + Wo·ao + bo  (tf32)
    wo_tc<<<dim3(NTOK / 128, CH / 128, BATCH), GT, smTF>>>(wo, ao, out, bo, x);
}

// round 13
// speedup vs baseline: 2.9946x; 1.1245x over previous
#include <cuda_runtime.h>
#include <cuda_fp16.h>
#include <math.h>

#define BATCH  2
#define CH     512
#define NTOK   4096
#define GROUPS 32
#define CPG    16
#define EPS    1e-6f

#define BK     64       // fp16 K-slab
#define MKPH   72       // fp16 row-major smem pitch (halfs): 64 + 8 pad
#define GT     128      // 4 warps, 2x2 warp grid, 64x64 warp tiles
#define NSTG   3
#define TFH    (128 * MKPH)            // halfs per staged tile
#define SMH    (NSTG * 2 * TFH * 2)    // dyn smem bytes = 110592

// ---------------- scratch ----------------
__device__ float  g_h  [(size_t)BATCH * CH * NTOK];   // groupnorm out [b][c][n]
__device__ __half g_ht [(size_t)BATCH * NTOK * CH];   // h^T  [b][n][c]
__device__ __half g_wh [(size_t)4 * CH * CH];         // wq,wk,wv,wo (half)
__device__ __half g_qt [(size_t)BATCH * NTOK * CH];   // q^T [b][nq][c]
__device__ __half g_kt [(size_t)BATCH * NTOK * CH];   // k^T [b][nk][c]
__device__ __half g_vh [(size_t)BATCH * CH * NTOK];   // v   [b][c][nk]
__device__ __half g_sh [(size_t)BATCH * NTOK * NTOK]; // exp-scores [b][nq][nk]
__device__ __half g_aot[(size_t)BATCH * NTOK * CH];   // attn-out^T [b][nq][c]
__device__ float  g_rsum[(size_t)BATCH * NTOK];

// ---------------- GroupNorm -> float h[c][n] (+ rsum zeroing) ----------------
__global__ void gn_kernel(const float* __restrict__ x,
                          const float* __restrict__ gamma,
                          const float* __restrict__ beta)
{
    const int gid = blockIdx.x * blockDim.x + threadIdx.x;
    if (gid < BATCH * NTOK) g_rsum[gid] = 0.f;

    const int bg = blockIdx.x;
    const int b = bg / GROUPS, g = bg % GROUPS;
    const size_t base = ((size_t)b * CH + (size_t)g * CPG) * NTOK;
    const float* xp = x + base;
    float* hp = g_h + base;
    const int M = CPG * NTOK;

    float s = 0.f, s2 = 0.f;
    for (int i = threadIdx.x * 4; i < M; i += blockDim.x * 4) {
        float4 v = *(const float4*)&xp[i];
        s  += v.x + v.y + v.z + v.w;
        s2 += v.x*v.x + v.y*v.y + v.z*v.z + v.w*v.w;
    }
    __shared__ float shs[8], shs2[8], shbc[2];
    #pragma unroll
    for (int o = 16; o; o >>= 1) {
        s  += __shfl_xor_sync(0xFFFFFFFFu, s,  o);
        s2 += __shfl_xor_sync(0xFFFFFFFFu, s2, o);
    }
    const int wid = threadIdx.x >> 5, lane = threadIdx.x & 31;
    if (!lane) { shs[wid] = s; shs2[wid] = s2; }
    __syncthreads();
    if (threadIdx.x == 0) {
        float ts = 0.f, ts2 = 0.f;
        #pragma unroll
        for (int i = 0; i < 8; i++) { ts += shs[i]; ts2 += shs2[i]; }
        const float mean = ts / (float)M;
        const float var  = ts2 / (float)M - mean * mean;
        shbc[0] = mean;
        shbc[1] = rsqrtf(var + EPS);
    }
    __syncthreads();
    const float mean = shbc[0], rstd = shbc[1];
    for (int i = threadIdx.x * 4; i < M; i += blockDim.x * 4) {
        const int c = g * CPG + (i >> 12);
        const float ga = gamma[c] * rstd;
        const float be = beta[c] - mean * ga;
        float4 v = *(const float4*)&xp[i];
        float4 o;
        o.x = v.x * ga + be; o.y = v.y * ga + be;
        o.z = v.z * ga + be; o.w = v.w * ga + be;
        *(float4*)&hp[i] = o;
    }
}

// ---------------- weight fp32 -> fp16 ----------------
struct W4 { const float* w[4]; };
__global__ void cvt_w(W4 ws)
{
    const size_t i = (size_t)blockIdx.x * blockDim.x + threadIdx.x;  // 4*CH*CH total
    const int wsel = (int)(i >> 18);          // CH*CH = 262144 = 2^18
    const int idx  = (int)(i & 262143);
    g_wh[i] = __float2half_rn(ws.w[wsel][idx]);
}

// ---------------- transpose+convert: h[c][n] fp32 -> ht[n][c] fp16 ----------------
__global__ void tr_h()
{
    __shared__ float t[32][33];
    const int b  = blockIdx.z;
    const int n0 = blockIdx.x * 32, c0 = blockIdx.y * 32;
    const int tx = threadIdx.x, ty = threadIdx.y;   // 32 x 8
    const float* hb = g_h + (size_t)b * CH * NTOK;
    __half* htb = g_ht + (size_t)b * NTOK * CH;
    #pragma unroll
    for (int j = 0; j < 32; j += 8)
        t[ty + j][tx] = hb[(size_t)(c0 + ty + j) * NTOK + n0 + tx];
    __syncthreads();
    #pragma unroll
    for (int j = 0; j < 32; j += 8)
        htb[(size_t)(n0 + ty + j) * CH + c0 + tx] = __float2half_rn(t[tx][ty + j]);
}

// ---------------- cp.async staging (fp16, 128 rows x 64 halfs) ----------------
__device__ __forceinline__ void cpa16h(__half* dst, const __half* src)
{
    unsigned s = (unsigned)__cvta_generic_to_shared(dst);
    asm volatile("cp.async.cg.shared.global [%0], [%1], 16;" :: "r"(s), "l"(src));
}
__device__ __forceinline__ void stage_h(__half* dst, const __half* src, int ld, int tid)
{
    #pragma unroll
    for (int i = 0; i < 8; i++) {
        const int c = tid + (i << 7);
        const int row = c >> 3, k8 = (c & 7) << 3;
        cpa16h(dst + row * MKPH + k8, src + (size_t)row * ld + k8);
    }
}
__device__ __forceinline__ unsigned ld32s(const __half* p) { return *(const unsigned*)p; }

// ================= fp16 tensor-core GEMM =================
// C[m,n] = scale * (sum_k A[m,k]*B[n,k]) + bias[m]  [exp + rowsum[m]] [/ rsum[n]]
// omode: 0 = fp32 [m][n] (+resid), 1 = half [m][n], 2 = half transposed [n][m]
template<bool DO_EXP, bool COLSCALE>
__device__ __forceinline__
void gemmh_body(const __half* __restrict__ A,
                const __half* __restrict__ Bm,
                void* __restrict__ Cv,
                const float* __restrict__ bias,
                const float* __restrict__ resid,
                float* __restrict__ rsum,
                int K, int lda, int ldb, int ldc,
                float scale, int omode, int m0, int n0)
{
    extern __shared__ __half dynh[];
    __half* SA = dynh;
    __half* SB = dynh + NSTG * TFH;

    const int tid = threadIdx.x;
    const int warp = tid >> 5, lane = tid & 31;
    const int wm = (warp >> 1) * 64;
    const int wn = (warp & 1) * 64;
    const int grp = lane >> 2;
    const int tig = lane & 3;

    const __half* At = A + (size_t)m0 * lda;
    const __half* Bt = Bm + (size_t)n0 * ldb;
    const int nslab = K / BK;

    stage_h(SA, At, lda, tid);
    stage_h(SB, Bt, ldb, tid);
    asm volatile("cp.async.commit_group;");
    if (1 < nslab) {
        stage_h(SA + TFH, At + BK, lda, tid);
        stage_h(SB + TFH, Bt + BK, ldb, tid);
        asm volatile("cp.async.commit_group;");
    }

    float acc[4][8][4];
    #pragma unroll
    for (int a = 0; a < 4; a++)
        #pragma unroll
        for (int b = 0; b < 8; b++)
            #pragma unroll
            for (int c = 0; c < 4; c++) acc[a][b][c] = 0.f;

    int buf = 0;
    for (int s = 0; s < nslab; s++) {
        if (s + 1 < nslab) asm volatile("cp.async.wait_group 1;");
        else               asm volatile("cp.async.wait_group 0;");
        __syncthreads();

        if (s + 2 < nslab) {
            const int nb = (buf + 2 >= NSTG) ? (buf + 2 - NSTG) : (buf + 2);
            stage_h(SA + nb * TFH, At + (size_t)(s + 2) * BK, lda, tid);
            stage_h(SB + nb * TFH, Bt + (size_t)(s + 2) * BK, ldb, tid);
            asm volatile("cp.async.commit_group;");
        }

        const __half* sa = SA + buf * TFH;
        const __half* sb = SB + buf * TFH;
        #pragma unroll
        for (int kc = 0; kc < BK; kc += 16) {
            const int k0i = kc + (tig << 1);
            unsigned af[4][4], bf[8][2];
            #pragma unroll
            for (int mi = 0; mi < 4; mi++) {
                const int m = wm + mi * 16 + grp;
                af[mi][0] = ld32s(sa + m * MKPH + k0i);
                af[mi][1] = ld32s(sa + (m + 8) * MKPH + k0i);
                af[mi][2] = ld32s(sa + m * MKPH + k0i + 8);
                af[mi][3] = ld32s(sa + (m + 8) * MKPH + k0i + 8);
            }
            #pragma unroll
            for (int nj = 0; nj < 8; nj++) {
                const int n = wn + nj * 8 + grp;
                bf[nj][0] = ld32s(sb + n * MKPH + k0i);
                bf[nj][1] = ld32s(sb + n * MKPH + k0i + 8);
            }
            #pragma unroll
            for (int mi = 0; mi < 4; mi++)
                #pragma unroll
                for (int nj = 0; nj < 8; nj++) {
                    asm volatile(
                        "mma.sync.aligned.m16n8k16.row.col.f32.f16.f16.f32 "
                        "{%0,%1,%2,%3}, {%4,%5,%6,%7}, {%8,%9}, {%0,%1,%2,%3};"
                        : "+f"(acc[mi][nj][0]), "+f"(acc[mi][nj][1]),
                          "+f"(acc[mi][nj][2]), "+f"(acc[mi][nj][3])
                        : "r"(af[mi][0]), "r"(af[mi][1]),
                          "r"(af[mi][2]), "r"(af[mi][3]),
                          "r"(bf[nj][0]), "r"(bf[nj][1]));
                }
        }
        buf = (buf + 1 >= NSTG) ? 0 : buf + 1;
    }

    // ---- epilogue
    float inv[8][2];
    if (COLSCALE) {
        #pragma unroll
        for (int nj = 0; nj < 8; nj++) {
            const int n = n0 + wn + nj * 8 + (tig << 1);
            inv[nj][0] = 1.f / rsum[n];
            inv[nj][1] = 1.f / rsum[n + 1];
        }
    }
    float rsA[4], rsB[4];
    #pragma unroll
    for (int mi = 0; mi < 4; mi++) { rsA[mi] = 0.f; rsB[mi] = 0.f; }

    #pragma unroll
    for (int mi = 0; mi < 4; mi++) {
        const int mA = m0 + wm + mi * 16 + grp;
        const int mB = mA + 8;
        const float bvA = bias ? bias[mA] : 0.f;
        const float bvB = bias ? bias[mB] : 0.f;
        #pragma unroll
        for (int nj = 0; nj < 8; nj++) {
            const int n = n0 + wn + nj * 8 + (tig << 1);
            float2 o0, o1;
            o0.x = acc[mi][nj][0] * scale + bvA;
            o0.y = acc[mi][nj][1] * scale + bvA;
            o1.x = acc[mi][nj][2] * scale + bvB;
            o1.y = acc[mi][nj][3] * scale + bvB;
            if (DO_EXP) {
                o0.x = __expf(o0.x); o0.y = __expf(o0.y);
                o1.x = __expf(o1.x); o1.y = __expf(o1.y);
                rsA[mi] += o0.x + o0.y;
                rsB[mi] += o1.x + o1.y;
            }
            if (COLSCALE) {
                o0.x *= inv[nj][0]; o0.y *= inv[nj][1];
                o1.x *= inv[nj][0]; o1.y *= inv[nj][1];
            }
            if (omode == 0) {
                float* fC = (float*)Cv;
                if (resid) {
                    float2 r0 = *(const float2*)&resid[(size_t)mA * ldc + n];
                    float2 r1 = *(const float2*)&resid[(size_t)mB * ldc + n];
                    o0.x += r0.x; o0.y += r0.y;
                    o1.x += r1.x; o1.y += r1.y;
                }
                *(float2*)&fC[(size_t)mA * ldc + n] = o0;
                *(float2*)&fC[(size_t)mB * ldc + n] = o1;
            } else if (omode == 1) {
                __half* hC = (__half*)Cv;
                *(__half2*)&hC[(size_t)mA * ldc + n] = __floats2half2_rn(o0.x, o0.y);
                *(__half2*)&hC[(size_t)mB * ldc + n] = __floats2half2_rn(o1.x, o1.y);
            } else {
                __half* hC = (__half*)Cv;
                hC[(size_t)n * ldc + mA]       = __float2half_rn(o0.x);
                hC[(size_t)(n + 1) * ldc + mA] = __float2half_rn(o0.y);
                hC[(size_t)n * ldc + mB]       = __float2half_rn(o1.x);
                hC[(size_t)(n + 1) * ldc + mB] = __float2half_rn(o1.y);
            }
        }
    }
    if (DO_EXP) {
        #pragma unroll
        for (int mi = 0; mi < 4; mi++) {
            float a = rsA[mi], b = rsB[mi];
            a += __shfl_xor_sync(0xFFFFFFFFu, a, 1);
            a += __shfl_xor_sync(0xFFFFFFFFu, a, 2);
            b += __shfl_xor_sync(0xFFFFFFFFu, b, 1);
            b += __shfl_xor_sync(0xFFFFFFFFu, b, 2);
            if (tig == 0) {
                const int mA = m0 + wm + mi * 16 + grp;
                atomicAdd(&rsum[mA], a);
                atomicAdd(&rsum[mA + 8], b);
            }
        }
    }
}

template<bool DO_EXP, bool COLSCALE>
__global__ __launch_bounds__(GT, 2)
void gemm_h(const __half* __restrict__ A,  size_t sAb,
            const __half* __restrict__ Bm, size_t sBb,
            void* __restrict__ Cv,         size_t sCb,  // elements
            const float* __restrict__ bias,
            const float* __restrict__ resid, size_t sRb,
            float* rsum,
            int K, int lda, int ldb, int ldc, float scale, int omode)
{
    const int bz = blockIdx.z;
    char* Cb = (char*)Cv + sCb * (omode == 0 ? 4 : 2) * bz;
    gemmh_body<DO_EXP, COLSCALE>(
        A + sAb * bz, Bm + sBb * bz, (void*)Cb,
        bias, resid ? resid + sRb * bz : nullptr,
        rsum ? rsum + (size_t)NTOK * bz : nullptr,
        K, lda, ldb, ldc, scale, omode,
        blockIdx.y * 128, blockIdx.x * 128);
}

struct QKVH {
    const __half* w[3];
    const float*  b[3];
    __half*       o[3];
    int           ldc[3];
    int           omode[3];
    size_t        ostride[3];
};

__global__ __launch_bounds__(GT, 2)
void qkv_h(QKVH a, const __half* __restrict__ ht)
{
    const int pj = blockIdx.z / BATCH;
    const int bz = blockIdx.z % BATCH;
    const size_t sNC = (size_t)NTOK * CH;
    gemmh_body<false, false>(
        a.w[pj], ht + sNC * bz, (void*)(a.o[pj] + a.ostride[pj] * bz),
        a.b[pj], nullptr, nullptr,
        CH, CH, CH, a.ldc[pj], 1.f, a.omode[pj],
        blockIdx.y * 128, blockIdx.x * 128);
}

// ---------------- launcher ----------------
extern "C" void kernel_launch(void* const* d_in, const int* in_sizes, int n_in,
                              void* d_out, int out_size)
{
    const float* x     = (const float*)d_in[0];
    const float* gamma = (const float*)d_in[1];
    const float* beta  = (const float*)d_in[2];
    const float* wq    = (const float*)d_in[3];
    const float* bq    = (const float*)d_in[4];
    const float* wk    = (const float*)d_in[5];
    const float* bk    = (const float*)d_in[6];
    const float* wv    = (const float*)d_in[7];
    const float* bv    = (const float*)d_in[8];
    const float* wo    = (const float*)d_in[9];
    const float* bo    = (const float*)d_in[10];
    float* out = (float*)d_out;

    float *rsum;
    __half *ht, *wh, *qt, *kt, *vh, *sh, *aot;
    cudaGetSymbolAddress((void**)&ht,   g_ht);
    cudaGetSymbolAddress((void**)&wh,   g_wh);
    cudaGetSymbolAddress((void**)&qt,   g_qt);
    cudaGetSymbolAddress((void**)&kt,   g_kt);
    cudaGetSymbolAddress((void**)&vh,   g_vh);
    cudaGetSymbolAddress((void**)&sh,   g_sh);
    cudaGetSymbolAddress((void**)&aot,  g_aot);
    cudaGetSymbolAddress((void**)&rsum, g_rsum);

    const size_t sNC = (size_t)NTOK * CH;
    const size_t sNN = (size_t)NTOK * NTOK;
    const size_t sCN = (size_t)CH * NTOK;
    const size_t WSZ = (size_t)CH * CH;
    const float attn_scale = 0.044194173824159216f;   // 512^-0.5

    static bool attr_done = false;
    if (!attr_done) {
        cudaFuncSetAttribute(qkv_h, cudaFuncAttributeMaxDynamicSharedMemorySize, SMH);
        cudaFuncSetAttribute(gemm_h<true, false>,
                             cudaFuncAttributeMaxDynamicSharedMemorySize, SMH);
        cudaFuncSetAttribute(gemm_h<false, true>,
                             cudaFuncAttributeMaxDynamicSharedMemorySize, SMH);
        cudaFuncSetAttribute(gemm_h<false, false>,
                             cudaFuncAttributeMaxDynamicSharedMemorySize, SMH);
        attr_done = true;
    }

    // 1) GroupNorm -> g_h (float), zero rsum
    gn_kernel<<<BATCH * GROUPS, 256>>>(x, gamma, beta);

    // 2) weights -> half ; h -> h^T half
    W4 ws; ws.w[0] = wq; ws.w[1] = wk; ws.w[2] = wv; ws.w[3] = wo;
    cvt_w<<<(int)(4 * WSZ / 256), 256>>>(ws);
    tr_h<<<dim3(NTOK / 32, CH / 32, BATCH), dim3(32, 8)>>>();

    // 3) Q/K/V projections (fp16): q^T, k^T transposed; v normal
    QKVH qa;
    qa.w[0] = wh;           qa.w[1] = wh + WSZ;      qa.w[2] = wh + 2 * WSZ;
    qa.b[0] = bq;           qa.b[1] = bk;            qa.b[2] = bv;
    qa.o[0] = qt;           qa.o[1] = kt;            qa.o[2] = vh;
    qa.ldc[0] = CH;         qa.ldc[1] = CH;          qa.ldc[2] = NTOK;
    qa.omode[0] = 2;        qa.omode[1] = 2;         qa.omode[2] = 1;
    qa.ostride[0] = sNC;    qa.ostride[1] = sNC;     qa.ostride[2] = sCN;
    qkv_h<<<dim3(NTOK / 128, CH / 128, 3 * BATCH), GT, SMH>>>(qa, ht);

    // 4) exp-scores: s[nq][nk] = exp(scale * q^T·k), rowsum[nq]
    gemm_h<true, false><<<dim3(NTOK / 128, NTOK / 128, BATCH), GT, SMH>>>(
        qt, sNC, kt, sNC, sh, sNN, nullptr, nullptr, 0, rsum,
        CH, CH, CH, NTOK, attn_scale, 1);

    // 5) ao^T[nq][c] = (v·s^T)/rsum[nq]   (transposed half out)
    gemm_h<false, true><<<dim3(NTOK / 128, CH / 128, BATCH), GT, SMH>>>(
        vh, sCN, sh, sNN, aot, sNC, nullptr, nullptr, 0, rsum,
        NTOK, NTOK, NTOK, CH, 1.f, 2);

    // 6) out = x + wo·ao + bo  (fp32 out + residual)
    gemm_h<false, false><<<dim3(NTOK / 128, CH / 128, BATCH), GT, SMH>>>(
        wh + 3 * WSZ, 0, aot, sNC, out, sCN, bo, x, sCN, nullptr,
        CH, CH, CH, NTOK, 1.f, 0);
}

// round 14
// speedup vs baseline: 3.1300x; 1.0452x over previous
#include <cuda_runtime.h>
#include <cuda_fp16.h>
#include <math.h>

#define BATCH  2
#define CH     512
#define NTOK   4096
#define GROUPS 32
#define CPG    16
#define EPS    1e-6f

#define BK     64       // fp16 K-slab
#define MKPH   72       // fp16 row-major smem pitch (halfs): 64 + 8 pad
#define GT     128      // 4 warps, 2x2 warp grid, 64x64 warp tiles
#define NSTG   3
#define TFH    (128 * MKPH)            // halfs per staged tile
#define SMH    (NSTG * 2 * TFH * 2)    // dyn smem bytes = 110592

// ---------------- scratch ----------------
__device__ __half g_ht [(size_t)BATCH * NTOK * CH];   // h^T  [b][n][c]
__device__ __half g_wh [(size_t)4 * CH * CH];         // wq,wk,wv,wo (half)
__device__ __half g_qt [(size_t)BATCH * NTOK * CH];   // q^T [b][nq][c]
__device__ __half g_kt [(size_t)BATCH * NTOK * CH];   // k^T [b][nk][c]
__device__ __half g_vh [(size_t)BATCH * CH * NTOK];   // v   [b][c][nk]
__device__ __half g_sh [(size_t)BATCH * NTOK * NTOK]; // exp-scores [b][nq][nk]
__device__ __half g_aot[(size_t)BATCH * NTOK * CH];   // attn-out^T [b][nq][c]
__device__ float  g_rsum[(size_t)BATCH * NTOK];

// ---------------- GroupNorm -> ht[n][c] fp16 directly (+ rsum zeroing) ----------------
__global__ void gn_kernel(const float* __restrict__ x,
                          const float* __restrict__ gamma,
                          const float* __restrict__ beta)
{
    const int gid = blockIdx.x * blockDim.x + threadIdx.x;
    if (gid < BATCH * NTOK) g_rsum[gid] = 0.f;

    const int bg = blockIdx.x;
    const int b = bg / GROUPS, g = bg % GROUPS;
    const size_t base = ((size_t)b * CH + (size_t)g * CPG) * NTOK;
    const float* xp = x + base;
    __half* htb = g_ht + (size_t)b * NTOK * CH + g * CPG;
    const int M = CPG * NTOK;
    const int t = threadIdx.x;     // 256 threads

    // ---- pass 1: stats
    float s = 0.f, s2 = 0.f;
    for (int i = t * 4; i < M; i += 1024) {
        float4 v = *(const float4*)&xp[i];
        s  += v.x + v.y + v.z + v.w;
        s2 += v.x*v.x + v.y*v.y + v.z*v.z + v.w*v.w;
    }
    __shared__ float shs[8], shs2[8];
    __shared__ float shga[CPG], shbe[CPG];
    #pragma unroll
    for (int o = 16; o; o >>= 1) {
        s  += __shfl_xor_sync(0xFFFFFFFFu, s,  o);
        s2 += __shfl_xor_sync(0xFFFFFFFFu, s2, o);
    }
    const int wid = t >> 5, lane = t & 31;
    if (!lane) { shs[wid] = s; shs2[wid] = s2; }
    __syncthreads();
    if (t == 0) {
        float ts = 0.f, ts2 = 0.f;
        #pragma unroll
        for (int i = 0; i < 8; i++) { ts += shs[i]; ts2 += shs2[i]; }
        const float mean = ts / (float)M;
        const float var  = ts2 / (float)M - mean * mean;
        shs[0] = mean;
        shs2[0] = rsqrtf(var + EPS);
    }
    __syncthreads();
    if (t < CPG) {
        const float ga = gamma[g * CPG + t] * shs2[0];
        shga[t] = ga;
        shbe[t] = beta[g * CPG + t] - shs[0] * ga;
    }
    __syncthreads();

    // ---- pass 2: normalize + transpose to ht[n][c] (smem bounce)
    __shared__ float tile[CPG][257];
    for (int n0 = 0; n0 < NTOK; n0 += 256) {
        #pragma unroll
        for (int c = 0; c < CPG; c++)
            tile[c][t] = xp[(size_t)c * NTOK + n0 + t] * shga[c] + shbe[c];
        __syncthreads();
        __half hv[CPG];
        #pragma unroll
        for (int c = 0; c < CPG; c++) hv[c] = __float2half_rn(tile[c][t]);
        *(uint4*)&htb[(size_t)(n0 + t) * CH] = *(uint4*)hv;            // 16 halves = 32B
        *(uint4*)&htb[(size_t)(n0 + t) * CH + 8] = *(uint4*)(hv + 8);
        __syncthreads();
    }
}

// ---------------- weight fp32 -> fp16 ----------------
struct W4 { const float* w[4]; };
__global__ void cvt_w(W4 ws)
{
    const size_t i = (size_t)blockIdx.x * blockDim.x + threadIdx.x;
    const int wsel = (int)(i >> 18);
    const int idx  = (int)(i & 262143);
    g_wh[i] = __float2half_rn(ws.w[wsel][idx]);
}

// ---------------- cp.async staging (fp16, 128 rows x 64 halfs) ----------------
__device__ __forceinline__ void cpa16h(__half* dst, const __half* src)
{
    unsigned s = (unsigned)__cvta_generic_to_shared(dst);
    asm volatile("cp.async.cg.shared.global [%0], [%1], 16;" :: "r"(s), "l"(src));
}
__device__ __forceinline__ void stage_h(__half* dst, const __half* src, int ld, int tid)
{
    #pragma unroll
    for (int i = 0; i < 8; i++) {
        const int c = tid + (i << 7);
        const int row = c >> 3, k8 = (c & 7) << 3;
        cpa16h(dst + row * MKPH + k8, src + (size_t)row * ld + k8);
    }
}
__device__ __forceinline__ unsigned ld32s(const __half* p) { return *(const unsigned*)p; }

// ================= fp16 tensor-core GEMM =================
// C[m,n] = scale * (sum_k A[m,k]*B[n,k]) + bias[m]  [exp + rowsum[m]] [/ rsum[n]]
// omode: 0 = fp32 [m][n] (+resid), 1 = half [m][n], 2 = half transposed [n][m]
template<bool DO_EXP, bool COLSCALE>
__device__ __forceinline__
void gemmh_body(const __half* __restrict__ A,
                const __half* __restrict__ Bm,
                void* __restrict__ Cv,
                const float* __restrict__ bias,
                const float* __restrict__ resid,
                float* __restrict__ rsum,
                int K, int lda, int ldb, int ldc,
                float scale, int omode, int m0, int n0)
{
    extern __shared__ __half dynh[];
    __half* SA = dynh;
    __half* SB = dynh + NSTG * TFH;

    const int tid = threadIdx.x;
    const int warp = tid >> 5, lane = tid & 31;
    const int wm = (warp >> 1) * 64;
    const int wn = (warp & 1) * 64;
    const int grp = lane >> 2;
    const int tig = lane & 3;

    const __half* At = A + (size_t)m0 * lda;
    const __half* Bt = Bm + (size_t)n0 * ldb;
    const int nslab = K / BK;

    stage_h(SA, At, lda, tid);
    stage_h(SB, Bt, ldb, tid);
    asm volatile("cp.async.commit_group;");
    if (1 < nslab) {
        stage_h(SA + TFH, At + BK, lda, tid);
        stage_h(SB + TFH, Bt + BK, ldb, tid);
        asm volatile("cp.async.commit_group;");
    }

    float acc[4][8][4];
    #pragma unroll
    for (int a = 0; a < 4; a++)
        #pragma unroll
        for (int b = 0; b < 8; b++)
            #pragma unroll
            for (int c = 0; c < 4; c++) acc[a][b][c] = 0.f;

    unsigned af[2][4][4], bf[2][8][2];

    int buf = 0;
    for (int s = 0; s < nslab; s++) {
        if (s + 1 < nslab) asm volatile("cp.async.wait_group 1;");
        else               asm volatile("cp.async.wait_group 0;");
        __syncthreads();

        if (s + 2 < nslab) {
            const int nb = (buf + 2 >= NSTG) ? (buf + 2 - NSTG) : (buf + 2);
            stage_h(SA + nb * TFH, At + (size_t)(s + 2) * BK, lda, tid);
            stage_h(SB + nb * TFH, Bt + (size_t)(s + 2) * BK, ldb, tid);
            asm volatile("cp.async.commit_group;");
        }

        const __half* sa = SA + buf * TFH;
        const __half* sb = SB + buf * TFH;

        // fragment loader for one kc step into buffer p
        auto ldfr = [&](int p, int kc) {
            const int k0i = kc + (tig << 1);
            #pragma unroll
            for (int mi = 0; mi < 4; mi++) {
                const int m = wm + mi * 16 + grp;
                af[p][mi][0] = ld32s(sa + m * MKPH + k0i);
                af[p][mi][1] = ld32s(sa + (m + 8) * MKPH + k0i);
                af[p][mi][2] = ld32s(sa + m * MKPH + k0i + 8);
                af[p][mi][3] = ld32s(sa + (m + 8) * MKPH + k0i + 8);
            }
            #pragma unroll
            for (int nj = 0; nj < 8; nj++) {
                const int n = wn + nj * 8 + grp;
                bf[p][nj][0] = ld32s(sb + n * MKPH + k0i);
                bf[p][nj][1] = ld32s(sb + n * MKPH + k0i + 8);
            }
        };

        ldfr(0, 0);
        #pragma unroll
        for (int kc = 0; kc < BK; kc += 16) {
            const int p = (kc >> 4) & 1;
            if (kc + 16 < BK) ldfr(p ^ 1, kc + 16);
            #pragma unroll
            for (int mi = 0; mi < 4; mi++)
                #pragma unroll
                for (int nj = 0; nj < 8; nj++) {
                    asm volatile(
                        "mma.sync.aligned.m16n8k16.row.col.f32.f16.f16.f32 "
                        "{%0,%1,%2,%3}, {%4,%5,%6,%7}, {%8,%9}, {%0,%1,%2,%3};"
                        : "+f"(acc[mi][nj][0]), "+f"(acc[mi][nj][1]),
                          "+f"(acc[mi][nj][2]), "+f"(acc[mi][nj][3])
                        : "r"(af[p][mi][0]), "r"(af[p][mi][1]),
                          "r"(af[p][mi][2]), "r"(af[p][mi][3]),
                          "r"(bf[p][nj][0]), "r"(bf[p][nj][1]));
                }
        }
        buf = (buf + 1 >= NSTG) ? 0 : buf + 1;
    }

    // ---- epilogue
    float inv[8][2];
    if (COLSCALE) {
        #pragma unroll
        for (int nj = 0; nj < 8; nj++) {
            const int n = n0 + wn + nj * 8 + (tig << 1);
            inv[nj][0] = 1.f / rsum[n];
            inv[nj][1] = 1.f / rsum[n + 1];
        }
    }
    float rsA[4], rsB[4];
    #pragma unroll
    for (int mi = 0; mi < 4; mi++) { rsA[mi] = 0.f; rsB[mi] = 0.f; }

    #pragma unroll
    for (int mi = 0; mi < 4; mi++) {
        const int mA = m0 + wm + mi * 16 + grp;
        const int mB = mA + 8;
        const float bvA = bias ? bias[mA] : 0.f;
        const float bvB = bias ? bias[mB] : 0.f;
        #pragma unroll
        for (int nj = 0; nj < 8; nj++) {
            const int n = n0 + wn + nj * 8 + (tig << 1);
            float2 o0, o1;
            o0.x = acc[mi][nj][0] * scale + bvA;
            o0.y = acc[mi][nj][1] * scale + bvA;
            o1.x = acc[mi][nj][2] * scale + bvB;
            o1.y = acc[mi][nj][3] * scale + bvB;
            if (DO_EXP) {
                o0.x = __expf(o0.x); o0.y = __expf(o0.y);
                o1.x = __expf(o1.x); o1.y = __expf(o1.y);
                rsA[mi] += o0.x + o0.y;
                rsB[mi] += o1.x + o1.y;
            }
            if (COLSCALE) {
                o0.x *= inv[nj][0]; o0.y *= inv[nj][1];
                o1.x *= inv[nj][0]; o1.y *= inv[nj][1];
            }
            if (omode == 0) {
                float* fC = (float*)Cv;
                if (resid) {
                    float2 r0 = *(const float2*)&resid[(size_t)mA * ldc + n];
                    float2 r1 = *(const float2*)&resid[(size_t)mB * ldc + n];
                    o0.x += r0.x; o0.y += r0.y;
                    o1.x += r1.x; o1.y += r1.y;
                }
                *(float2*)&fC[(size_t)mA * ldc + n] = o0;
                *(float2*)&fC[(size_t)mB * ldc + n] = o1;
            } else if (omode == 1) {
                __half* hC = (__half*)Cv;
                *(__half2*)&hC[(size_t)mA * ldc + n] = __floats2half2_rn(o0.x, o0.y);
                *(__half2*)&hC[(size_t)mB * ldc + n] = __floats2half2_rn(o1.x, o1.y);
            } else {
                __half* hC = (__half*)Cv;
                hC[(size_t)n * ldc + mA]       = __float2half_rn(o0.x);
                hC[(size_t)(n + 1) * ldc + mA] = __float2half_rn(o0.y);
                hC[(size_t)n * ldc + mB]       = __float2half_rn(o1.x);
                hC[(size_t)(n + 1) * ldc + mB] = __float2half_rn(o1.y);
            }
        }
    }
    if (DO_EXP) {
        #pragma unroll
        for (int mi = 0; mi < 4; mi++) {
            float a = rsA[mi], b = rsB[mi];
            a += __shfl_xor_sync(0xFFFFFFFFu, a, 1);
            a += __shfl_xor_sync(0xFFFFFFFFu, a, 2);
            b += __shfl_xor_sync(0xFFFFFFFFu, b, 1);
            b += __shfl_xor_sync(0xFFFFFFFFu, b, 2);
            if (tig == 0) {
                const int mA = m0 + wm + mi * 16 + grp;
                atomicAdd(&rsum[mA], a);
                atomicAdd(&rsum[mA + 8], b);
            }
        }
    }
}

template<bool DO_EXP, bool COLSCALE>
__global__ __launch_bounds__(GT, 2)
void gemm_h(const __half* __restrict__ A,  size_t sAb,
            const __half* __restrict__ Bm, size_t sBb,
            void* __restrict__ Cv,         size_t sCb,
            const float* __restrict__ bias,
            const float* __restrict__ resid, size_t sRb,
            float* rsum,
            int K, int lda, int ldb, int ldc, float scale, int omode)
{
    const int bz = blockIdx.z;
    char* Cb = (char*)Cv + sCb * (omode == 0 ? 4 : 2) * bz;
    gemmh_body<DO_EXP, COLSCALE>(
        A + sAb * bz, Bm + sBb * bz, (void*)Cb,
        bias, resid ? resid + sRb * bz : nullptr,
        rsum ? rsum + (size_t)NTOK * bz : nullptr,
        K, lda, ldb, ldc, scale, omode,
        blockIdx.y * 128, blockIdx.x * 128);
}

struct QKVH {
    const __half* w[3];
    const float*  b[3];
    __half*       o[3];
    int           ldc[3];
    int           omode[3];
    size_t        ostride[3];
};

__global__ __launch_bounds__(GT, 2)
void qkv_h(QKVH a, const __half* __restrict__ ht)
{
    const int pj = blockIdx.z / BATCH;
    const int bz = blockIdx.z % BATCH;
    const size_t sNC = (size_t)NTOK * CH;
    gemmh_body<false, false>(
        a.w[pj], ht + sNC * bz, (void*)(a.o[pj] + a.ostride[pj] * bz),
        a.b[pj], nullptr, nullptr,
        CH, CH, CH, a.ldc[pj], 1.f, a.omode[pj],
        blockIdx.y * 128, blockIdx.x * 128);
}

// ---------------- launcher ----------------
extern "C" void kernel_launch(void* const* d_in, const int* in_sizes, int n_in,
                              void* d_out, int out_size)
{
    const float* x     = (const float*)d_in[0];
    const float* gamma = (const float*)d_in[1];
    const float* beta  = (const float*)d_in[2];
    const float* wq    = (const float*)d_in[3];
    const float* bq    = (const float*)d_in[4];
    const float* wk    = (const float*)d_in[5];
    const float* bk    = (const float*)d_in[6];
    const float* wv    = (const float*)d_in[7];
    const float* bv    = (const float*)d_in[8];
    const float* wo    = (const float*)d_in[9];
    const float* bo    = (const float*)d_in[10];
    float* out = (float*)d_out;

    float *rsum;
    __half *ht, *wh, *qt, *kt, *vh, *sh, *aot;
    cudaGetSymbolAddress((void**)&ht,   g_ht);
    cudaGetSymbolAddress((void**)&wh,   g_wh);
    cudaGetSymbolAddress((void**)&qt,   g_qt);
    cudaGetSymbolAddress((void**)&kt,   g_kt);
    cudaGetSymbolAddress((void**)&vh,   g_vh);
    cudaGetSymbolAddress((void**)&sh,   g_sh);
    cudaGetSymbolAddress((void**)&aot,  g_aot);
    cudaGetSymbolAddress((void**)&rsum, g_rsum);

    const size_t sNC = (size_t)NTOK * CH;
    const size_t sNN = (size_t)NTOK * NTOK;
    const size_t sCN = (size_t)CH * NTOK;
    const size_t WSZ = (size_t)CH * CH;
    const float attn_scale = 0.044194173824159216f;   // 512^-0.5

    static bool attr_done = false;
    if (!attr_done) {
        cudaFuncSetAttribute(qkv_h, cudaFuncAttributeMaxDynamicSharedMemorySize, SMH);
        cudaFuncSetAttribute(gemm_h<true, false>,
                             cudaFuncAttributeMaxDynamicSharedMemorySize, SMH);
        cudaFuncSetAttribute(gemm_h<false, true>,
                             cudaFuncAttributeMaxDynamicSharedMemorySize, SMH);
        cudaFuncSetAttribute(gemm_h<false, false>,
                             cudaFuncAttributeMaxDynamicSharedMemorySize, SMH);
        attr_done = true;
    }

    // 1) GroupNorm -> ht (fp16, transposed), zero rsum
    gn_kernel<<<BATCH * GROUPS, 256>>>(x, gamma, beta);

    // 2) weights -> half
    W4 ws; ws.w[0] = wq; ws.w[1] = wk; ws.w[2] = wv; ws.w[3] = wo;
    cvt_w<<<(int)(4 * WSZ / 256), 256>>>(ws);

    // 3) Q/K/V projections (fp16): q^T, k^T transposed; v normal
    QKVH qa;
    qa.w[0] = wh;           qa.w[1] = wh + WSZ;      qa.w[2] = wh + 2 * WSZ;
    qa.b[0] = bq;           qa.b[1] = bk;            qa.b[2] = bv;
    qa.o[0] = qt;           qa.o[1] = kt;            qa.o[2] = vh;
    qa.ldc[0] = CH;         qa.ldc[1] = CH;          qa.ldc[2] = NTOK;
    qa.omode[0] = 2;        qa.omode[1] = 2;         qa.omode[2] = 1;
    qa.ostride[0] = sNC;    qa.ostride[1] = sNC;     qa.ostride[2] = sCN;
    qkv_h<<<dim3(NTOK / 128, CH / 128, 3 * BATCH), GT, SMH>>>(qa, ht);

    // 4) exp-scores: s[nq][nk] = exp(scale * q^T·k), rowsum[nq]
    gemm_h<true, false><<<dim3(NTOK / 128, NTOK / 128, BATCH), GT, SMH>>>(
        qt, sNC, kt, sNC, sh, sNN, nullptr, nullptr, 0, rsum,
        CH, CH, CH, NTOK, attn_scale, 1);

    // 5) ao^T[nq][c] = (v·s^T)/rsum[nq]   (transposed half out)
    gemm_h<false, true><<<dim3(NTOK / 128, CH / 128, BATCH), GT, SMH>>>(
        vh, sCN, sh, sNN, aot, sNC, nullptr, nullptr, 0, rsum,
        NTOK, NTOK, NTOK, CH, 1.f, 2);

    // 6) out = x + wo·ao + bo  (fp32 out + residual)
    gemm_h<false, false><<<dim3(NTOK / 128, CH / 128, BATCH), GT, SMH>>>(
        wh + 3 * WSZ, 0, aot, sNC, out, sCN, bo, x, sCN, nullptr,
        CH, CH, CH, NTOK, 1.f, 0);
}

// round 15
// speedup vs baseline: 3.2392x; 1.0349x over previous
#include <cuda_runtime.h>
#include <cuda_fp16.h>
#include <math.h>

#define BATCH  2
#define CH     512
#define NTOK   4096
#define GROUPS 32
#define CPG    16
#define EPS    1e-6f

#define BK     64       // fp16 K-slab
#define MKPH   72       // fp16 row-major smem pitch (halfs): 64 + 8 pad
#define GT     128      // 4 warps, 2x2 warp grid, 64x64 warp tiles
#define NSTG   3
#define TFH    (128 * MKPH)            // halfs per staged tile
#define SMH    (NSTG * 2 * TFH * 2)    // dyn smem bytes = 110592
#define BP     72                      // bounce tile pitch (halfs)

// ---------------- scratch ----------------
__device__ __half g_ht [(size_t)BATCH * NTOK * CH];   // h^T  [b][n][c]
__device__ __half g_wh [(size_t)4 * CH * CH];         // wq,wk,wv,wo (half)
__device__ __half g_qt [(size_t)BATCH * NTOK * CH];   // q^T [b][nq][c]
__device__ __half g_kt [(size_t)BATCH * NTOK * CH];   // k^T [b][nk][c]
__device__ __half g_vh [(size_t)BATCH * CH * NTOK];   // v   [b][c][nk]
__device__ __half g_sh [(size_t)BATCH * NTOK * NTOK]; // exp-scores [b][nq][nk]
__device__ __half g_aot[(size_t)BATCH * NTOK * CH];   // attn-out^T [b][nq][c]
__device__ float  g_rsum[(size_t)BATCH * NTOK];

// ---------------- GroupNorm -> ht[n][c] fp16 directly (+ rsum zeroing) ----------------
__global__ void gn_kernel(const float* __restrict__ x,
                          const float* __restrict__ gamma,
                          const float* __restrict__ beta)
{
    const int gid = blockIdx.x * blockDim.x + threadIdx.x;
    if (gid < BATCH * NTOK) g_rsum[gid] = 0.f;

    const int bg = blockIdx.x;
    const int b = bg / GROUPS, g = bg % GROUPS;
    const size_t base = ((size_t)b * CH + (size_t)g * CPG) * NTOK;
    const float* xp = x + base;
    __half* htb = g_ht + (size_t)b * NTOK * CH + g * CPG;
    const int M = CPG * NTOK;
    const int t = threadIdx.x;     // 256 threads

    float s = 0.f, s2 = 0.f;
    for (int i = t * 4; i < M; i += 1024) {
        float4 v = *(const float4*)&xp[i];
        s  += v.x + v.y + v.z + v.w;
        s2 += v.x*v.x + v.y*v.y + v.z*v.z + v.w*v.w;
    }
    __shared__ float shs[8], shs2[8];
    __shared__ float shga[CPG], shbe[CPG];
    #pragma unroll
    for (int o = 16; o; o >>= 1) {
        s  += __shfl_xor_sync(0xFFFFFFFFu, s,  o);
        s2 += __shfl_xor_sync(0xFFFFFFFFu, s2, o);
    }
    const int wid = t >> 5, lane = t & 31;
    if (!lane) { shs[wid] = s; shs2[wid] = s2; }
    __syncthreads();
    if (t == 0) {
        float ts = 0.f, ts2 = 0.f;
        #pragma unroll
        for (int i = 0; i < 8; i++) { ts += shs[i]; ts2 += shs2[i]; }
        const float mean = ts / (float)M;
        const float var  = ts2 / (float)M - mean * mean;
        shs[0] = mean;
        shs2[0] = rsqrtf(var + EPS);
    }
    __syncthreads();
    if (t < CPG) {
        const float ga = gamma[g * CPG + t] * shs2[0];
        shga[t] = ga;
        shbe[t] = beta[g * CPG + t] - shs[0] * ga;
    }
    __syncthreads();

    __shared__ float tile[CPG][257];
    for (int n0 = 0; n0 < NTOK; n0 += 256) {
        #pragma unroll
        for (int c = 0; c < CPG; c++)
            tile[c][t] = xp[(size_t)c * NTOK + n0 + t] * shga[c] + shbe[c];
        __syncthreads();
        __half hv[CPG];
        #pragma unroll
        for (int c = 0; c < CPG; c++) hv[c] = __float2half_rn(tile[c][t]);
        *(uint4*)&htb[(size_t)(n0 + t) * CH] = *(uint4*)hv;
        *(uint4*)&htb[(size_t)(n0 + t) * CH + 8] = *(uint4*)(hv + 8);
        __syncthreads();
    }
}

// ---------------- weight fp32 -> fp16 ----------------
struct W4 { const float* w[4]; };
__global__ void cvt_w(W4 ws)
{
    const size_t i = (size_t)blockIdx.x * blockDim.x + threadIdx.x;
    const int wsel = (int)(i >> 18);
    const int idx  = (int)(i & 262143);
    g_wh[i] = __float2half_rn(ws.w[wsel][idx]);
}

// ---------------- cp.async staging (fp16, 128 rows x 64 halfs) ----------------
__device__ __forceinline__ void cpa16h(__half* dst, const __half* src)
{
    unsigned s = (unsigned)__cvta_generic_to_shared(dst);
    asm volatile("cp.async.cg.shared.global [%0], [%1], 16;" :: "r"(s), "l"(src));
}
__device__ __forceinline__ void stage_h(__half* dst, const __half* src, int ld, int tid)
{
    #pragma unroll
    for (int i = 0; i < 8; i++) {
        const int c = tid + (i << 7);
        const int row = c >> 3, k8 = (c & 7) << 3;
        cpa16h(dst + row * MKPH + k8, src + (size_t)row * ld + k8);
    }
}
__device__ __forceinline__ unsigned ld32s(const __half* p) { return *(const unsigned*)p; }

// ================= fp16 tensor-core GEMM =================
// C[m,n] = scale * (sum_k A[m,k]*B[n,k]) + bias[m]  [exp + rowsum[m]] [/ rsum[n]]
// omode: 0 = fp32 [m][n] (+resid), 1 = half [m][n], 2 = half transposed [n][m]
template<bool DO_EXP, bool COLSCALE>
__device__ __forceinline__
void gemmh_body(const __half* __restrict__ A,
                const __half* __restrict__ Bm,
                void* __restrict__ Cv,
                const float* __restrict__ bias,
                const float* __restrict__ resid,
                float* __restrict__ rsum,
                int K, int lda, int ldb, int ldc,
                float scale, int omode, int m0, int n0)
{
    extern __shared__ __half dynh[];
    __half* SA = dynh;
    __half* SB = dynh + NSTG * TFH;

    const int tid = threadIdx.x;
    const int warp = tid >> 5, lane = tid & 31;
    const int wm = (warp >> 1) * 64;
    const int wn = (warp & 1) * 64;
    const int grp = lane >> 2;
    const int tig = lane & 3;

    const __half* At = A + (size_t)m0 * lda;
    const __half* Bt = Bm + (size_t)n0 * ldb;
    const int nslab = K / BK;

    stage_h(SA, At, lda, tid);
    stage_h(SB, Bt, ldb, tid);
    asm volatile("cp.async.commit_group;");
    if (1 < nslab) {
        stage_h(SA + TFH, At + BK, lda, tid);
        stage_h(SB + TFH, Bt + BK, ldb, tid);
        asm volatile("cp.async.commit_group;");
    }

    float acc[4][8][4];
    #pragma unroll
    for (int a = 0; a < 4; a++)
        #pragma unroll
        for (int b = 0; b < 8; b++)
            #pragma unroll
            for (int c = 0; c < 4; c++) acc[a][b][c] = 0.f;

    unsigned af[2][4][4], bf[2][8][2];

    int buf = 0;
    for (int s = 0; s < nslab; s++) {
        if (s + 1 < nslab) asm volatile("cp.async.wait_group 1;");
        else               asm volatile("cp.async.wait_group 0;");
        __syncthreads();

        if (s + 2 < nslab) {
            const int nb = (buf + 2 >= NSTG) ? (buf + 2 - NSTG) : (buf + 2);
            stage_h(SA + nb * TFH, At + (size_t)(s + 2) * BK, lda, tid);
            stage_h(SB + nb * TFH, Bt + (size_t)(s + 2) * BK, ldb, tid);
            asm volatile("cp.async.commit_group;");
        }

        const __half* sa = SA + buf * TFH;
        const __half* sb = SB + buf * TFH;

        auto ldfr = [&](int p, int kc) {
            const int k0i = kc + (tig << 1);
            #pragma unroll
            for (int mi = 0; mi < 4; mi++) {
                const int m = wm + mi * 16 + grp;
                af[p][mi][0] = ld32s(sa + m * MKPH + k0i);
                af[p][mi][1] = ld32s(sa + (m + 8) * MKPH + k0i);
                af[p][mi][2] = ld32s(sa + m * MKPH + k0i + 8);
                af[p][mi][3] = ld32s(sa + (m + 8) * MKPH + k0i + 8);
            }
            #pragma unroll
            for (int nj = 0; nj < 8; nj++) {
                const int n = wn + nj * 8 + grp;
                bf[p][nj][0] = ld32s(sb + n * MKPH + k0i);
                bf[p][nj][1] = ld32s(sb + n * MKPH + k0i + 8);
            }
        };

        ldfr(0, 0);
        #pragma unroll
        for (int kc = 0; kc < BK; kc += 16) {
            const int p = (kc >> 4) & 1;
            if (kc + 16 < BK) ldfr(p ^ 1, kc + 16);
            #pragma unroll
            for (int mi = 0; mi < 4; mi++)
                #pragma unroll
                for (int nj = 0; nj < 8; nj++) {
                    asm volatile(
                        "mma.sync.aligned.m16n8k16.row.col.f32.f16.f16.f32 "
                        "{%0,%1,%2,%3}, {%4,%5,%6,%7}, {%8,%9}, {%0,%1,%2,%3};"
                        : "+f"(acc[mi][nj][0]), "+f"(acc[mi][nj][1]),
                          "+f"(acc[mi][nj][2]), "+f"(acc[mi][nj][3])
                        : "r"(af[p][mi][0]), "r"(af[p][mi][1]),
                          "r"(af[p][mi][2]), "r"(af[p][mi][3]),
                          "r"(bf[p][nj][0]), "r"(bf[p][nj][1]));
                }
        }
        buf = (buf + 1 >= NSTG) ? 0 : buf + 1;
    }

    // ---- epilogue
    float inv[8][2];
    if (COLSCALE) {
        #pragma unroll
        for (int nj = 0; nj < 8; nj++) {
            const int n = n0 + wn + nj * 8 + (tig << 1);
            inv[nj][0] = 1.f / rsum[n];
            inv[nj][1] = 1.f / rsum[n + 1];
        }
    }
    float rsA[4], rsB[4];
    #pragma unroll
    for (int mi = 0; mi < 4; mi++) { rsA[mi] = 0.f; rsB[mi] = 0.f; }

    if (omode == 0) {
        #pragma unroll
        for (int mi = 0; mi < 4; mi++) {
            const int mA = m0 + wm + mi * 16 + grp;
            const int mB = mA + 8;
            const float bvA = bias ? bias[mA] : 0.f;
            const float bvB = bias ? bias[mB] : 0.f;
            #pragma unroll
            for (int nj = 0; nj < 8; nj++) {
                const int n = n0 + wn + nj * 8 + (tig << 1);
                float2 o0, o1;
                o0.x = acc[mi][nj][0] * scale + bvA;
                o0.y = acc[mi][nj][1] * scale + bvA;
                o1.x = acc[mi][nj][2] * scale + bvB;
                o1.y = acc[mi][nj][3] * scale + bvB;
                float* fC = (float*)Cv;
                if (resid) {
                    float2 r0 = *(const float2*)&resid[(size_t)mA * ldc + n];
                    float2 r1 = *(const float2*)&resid[(size_t)mB * ldc + n];
                    o0.x += r0.x; o0.y += r0.y;
                    o1.x += r1.x; o1.y += r1.y;
                }
                *(float2*)&fC[(size_t)mA * ldc + n] = o0;
                *(float2*)&fC[(size_t)mB * ldc + n] = o1;
            }
        }
    } else {
        // half outputs: smem-bounce for coalesced 16B stores
        __syncthreads();   // all warps done reading staged slabs; smem reuse safe
        __half* tile = dynh + warp * (64 * BP);
        #pragma unroll
        for (int mi = 0; mi < 4; mi++) {
            const int lm = mi * 16 + grp;
            const int mA = m0 + wm + lm;
            const float bvA = bias ? bias[mA] : 0.f;
            const float bvB = bias ? bias[mA + 8] : 0.f;
            #pragma unroll
            for (int nj = 0; nj < 8; nj++) {
                const int lnj = nj * 8 + (tig << 1);
                float2 o0, o1;
                o0.x = acc[mi][nj][0] * scale + bvA;
                o0.y = acc[mi][nj][1] * scale + bvA;
                o1.x = acc[mi][nj][2] * scale + bvB;
                o1.y = acc[mi][nj][3] * scale + bvB;
                if (DO_EXP) {
                    o0.x = __expf(o0.x); o0.y = __expf(o0.y);
                    o1.x = __expf(o1.x); o1.y = __expf(o1.y);
                    rsA[mi] += o0.x + o0.y;
                    rsB[mi] += o1.x + o1.y;
                }
                if (COLSCALE) {
                    o0.x *= inv[nj][0]; o0.y *= inv[nj][1];
                    o1.x *= inv[nj][0]; o1.y *= inv[nj][1];
                }
                if (omode == 1) {
                    *(__half2*)&tile[lm * BP + lnj]       = __floats2half2_rn(o0.x, o0.y);
                    *(__half2*)&tile[(lm + 8) * BP + lnj] = __floats2half2_rn(o1.x, o1.y);
                } else {
                    tile[lnj * BP + lm]           = __float2half_rn(o0.x);
                    tile[(lnj + 1) * BP + lm]     = __float2half_rn(o0.y);
                    tile[lnj * BP + lm + 8]       = __float2half_rn(o1.x);
                    tile[(lnj + 1) * BP + lm + 8] = __float2half_rn(o1.y);
                }
            }
        }
        __syncwarp();
        const int orow = (omode == 1) ? (m0 + wm) : (n0 + wn);
        const int ocol = (omode == 1) ? (n0 + wn) : (m0 + wm);
        __half* hC = (__half*)Cv;
        #pragma unroll
        for (int it = 0; it < 16; it++) {
            const int idx = it * 32 + lane;
            const int r = idx >> 3, seg = idx & 7;
            uint4 v = *(uint4*)&tile[r * BP + seg * 8];
            *(uint4*)&hC[(size_t)(orow + r) * ldc + ocol + seg * 8] = v;
        }
    }

    if (DO_EXP) {
        #pragma unroll
        for (int mi = 0; mi < 4; mi++) {
            float a = rsA[mi], b = rsB[mi];
            a += __shfl_xor_sync(0xFFFFFFFFu, a, 1);
            a += __shfl_xor_sync(0xFFFFFFFFu, a, 2);
            b += __shfl_xor_sync(0xFFFFFFFFu, b, 1);
            b += __shfl_xor_sync(0xFFFFFFFFu, b, 2);
            if (tig == 0) {
                const int mA = m0 + wm + mi * 16 + grp;
                atomicAdd(&rsum[mA], a);
                atomicAdd(&rsum[mA + 8], b);
            }
        }
    }
}

template<bool DO_EXP, bool COLSCALE>
__global__ __launch_bounds__(GT, 2)
void gemm_h(const __half* __restrict__ A,  size_t sAb,
            const __half* __restrict__ Bm, size_t sBb,
            void* __restrict__ Cv,         size_t sCb,
            const float* __restrict__ bias,
            const float* __restrict__ resid, size_t sRb,
            float* rsum,
            int K, int lda, int ldb, int ldc, float scale, int omode)
{
    const int bz = blockIdx.z;
    char* Cb = (char*)Cv + sCb * (omode == 0 ? 4 : 2) * bz;
    gemmh_body<DO_EXP, COLSCALE>(
        A + sAb * bz, Bm + sBb * bz, (void*)Cb,
        bias, resid ? resid + sRb * bz : nullptr,
        rsum ? rsum + (size_t)NTOK * bz : nullptr,
        K, lda, ldb, ldc, scale, omode,
        blockIdx.y * 128, blockIdx.x * 128);
}

struct QKVH {
    const __half* w[3];
    const float*  b[3];
    __half*       o[3];
    int           ldc[3];
    int           omode[3];
    size_t        ostride[3];
};

__global__ __launch_bounds__(GT, 2)
void qkv_h(QKVH a, const __half* __restrict__ ht)
{
    const int pj = blockIdx.z / BATCH;
    const int bz = blockIdx.z % BATCH;
    const size_t sNC = (size_t)NTOK * CH;
    gemmh_body<false, false>(
        a.w[pj], ht + sNC * bz, (void*)(a.o[pj] + a.ostride[pj] * bz),
        a.b[pj], nullptr, nullptr,
        CH, CH, CH, a.ldc[pj], 1.f, a.omode[pj],
        blockIdx.y * 128, blockIdx.x * 128);
}

// ---------------- launcher ----------------
extern "C" void kernel_launch(void* const* d_in, const int* in_sizes, int n_in,
                              void* d_out, int out_size)
{
    const float* x     = (const float*)d_in[0];
    const float* gamma = (const float*)d_in[1];
    const float* beta  = (const float*)d_in[2];
    const float* wq    = (const float*)d_in[3];
    const float* bq    = (const float*)d_in[4];
    const float* wk    = (const float*)d_in[5];
    const float* bk    = (const float*)d_in[6];
    const float* wv    = (const float*)d_in[7];
    const float* bv    = (const float*)d_in[8];
    const float* wo    = (const float*)d_in[9];
    const float* bo    = (const float*)d_in[10];
    float* out = (float*)d_out;

    float *rsum;
    __half *ht, *wh, *qt, *kt, *vh, *sh, *aot;
    cudaGetSymbolAddress((void**)&ht,   g_ht);
    cudaGetSymbolAddress((void**)&wh,   g_wh);
    cudaGetSymbolAddress((void**)&qt,   g_qt);
    cudaGetSymbolAddress((void**)&kt,   g_kt);
    cudaGetSymbolAddress((void**)&vh,   g_vh);
    cudaGetSymbolAddress((void**)&sh,   g_sh);
    cudaGetSymbolAddress((void**)&aot,  g_aot);
    cudaGetSymbolAddress((void**)&rsum, g_rsum);

    const size_t sNC = (size_t)NTOK * CH;
    const size_t sNN = (size_t)NTOK * NTOK;
    const size_t sCN = (size_t)CH * NTOK;
    const size_t WSZ = (size_t)CH * CH;
    const float attn_scale = 0.044194173824159216f;   // 512^-0.5

    static bool attr_done = false;
    if (!attr_done) {
        cudaFuncSetAttribute(qkv_h, cudaFuncAttributeMaxDynamicSharedMemorySize, SMH);
        cudaFuncSetAttribute(gemm_h<true, false>,
                             cudaFuncAttributeMaxDynamicSharedMemorySize, SMH);
        cudaFuncSetAttribute(gemm_h<false, true>,
                             cudaFuncAttributeMaxDynamicSharedMemorySize, SMH);
        cudaFuncSetAttribute(gemm_h<false, false>,
                             cudaFuncAttributeMaxDynamicSharedMemorySize, SMH);
        attr_done = true;
    }

    // 1) GroupNorm -> ht (fp16, transposed), zero rsum
    gn_kernel<<<BATCH * GROUPS, 256>>>(x, gamma, beta);

    // 2) weights -> half
    W4 ws; ws.w[0] = wq; ws.w[1] = wk; ws.w[2] = wv; ws.w[3] = wo;
    cvt_w<<<(int)(4 * WSZ / 256), 256>>>(ws);

    // 3) Q/K/V projections (fp16): q^T, k^T transposed; v normal
    QKVH qa;
    qa.w[0] = wh;           qa.w[1] = wh + WSZ;      qa.w[2] = wh + 2 * WSZ;
    qa.b[0] = bq;           qa.b[1] = bk;            qa.b[2] = bv;
    qa.o[0] = qt;           qa.o[1] = kt;            qa.o[2] = vh;
    qa.ldc[0] = CH;         qa.ldc[1] = CH;          qa.ldc[2] = NTOK;
    qa.omode[0] = 2;        qa.omode[1] = 2;         qa.omode[2] = 1;
    qa.ostride[0] = sNC;    qa.ostride[1] = sNC;     qa.ostride[2] = sCN;
    qkv_h<<<dim3(NTOK / 128, CH / 128, 3 * BATCH), GT, SMH>>>(qa, ht);

    // 4) exp-scores: s[nq][nk] = exp(scale * q^T·k), rowsum[nq]
    gemm_h<true, false><<<dim3(NTOK / 128, NTOK / 128, BATCH), GT, SMH>>>(
        qt, sNC, kt, sNC, sh, sNN, nullptr, nullptr, 0, rsum,
        CH, CH, CH, NTOK, attn_scale, 1);

    // 5) ao^T[nq][c] = (v·s^T)/rsum[nq]   (transposed half out)
    gemm_h<false, true><<<dim3(NTOK / 128, CH / 128, BATCH), GT, SMH>>>(
        vh, sCN, sh, sNN, aot, sNC, nullptr, nullptr, 0, rsum,
        NTOK, NTOK, NTOK, CH, 1.f, 2);

    // 6) out = x + wo·ao + bo  (fp32 out + residual)
    gemm_h<false, false><<<dim3(NTOK / 128, CH / 128, BATCH), GT, SMH>>>(
        wh + 3 * WSZ, 0, aot, sNC, out, sCN, bo, x, sCN, nullptr,
        CH, CH, CH, NTOK, 1.f, 0);
}